// round 1
// baseline (speedup 1.0000x reference)
#include <cuda_runtime.h>

#define NBATCH 2048
#define NN 62
#define CIN 512
#define NLAY 3
#define NHEAD 8
#define COUT 64
#define NTHREADS 512
#define KC 32

// Precomputed adjacency data: A_hat_l = A_l + I, dneg_l[n] = 1/rowsum(A_l)
__device__ float g_Ahat[NLAY * NN * NN];
__device__ float g_dneg[NLAY * NN];

__global__ void precompute_kernel(const float* __restrict__ L) {
    __shared__ float D1s[NN];
    int tid = threadIdx.x;
    if (tid < NN) {
        float s = 0.f;
        for (int m = 0; m < NN; m++) s += L[tid * NN + m];
        D1s[tid] = s;
    }
    __syncthreads();
    if (tid < NN) {
        g_dneg[tid] = 1.0f;  // layer 0: A = I, D = 1
        float d1 = D1s[tid];
        g_dneg[NN + tid] = (d1 == 0.f) ? 0.f : (1.f / d1);
        // D2[n] = rowsum(L@L)[n] = sum_k L[n,k] * rowsumL[k]
        float d2 = 0.f;
        for (int k = 0; k < NN; k++) d2 += L[tid * NN + k] * D1s[k];
        g_dneg[2 * NN + tid] = (d2 == 0.f) ? 0.f : (1.f / d2);
    }
    for (int idx = tid; idx < NN * NN; idx += blockDim.x) {
        int n = idx / NN, m = idx - n * NN;
        float eye = (n == m) ? 1.f : 0.f;
        g_Ahat[idx] = 2.f * eye;             // layer 0: I + I
        g_Ahat[NN * NN + idx] = L[idx] + eye; // layer 1: L + I
        float a2 = 0.f;
        for (int k = 0; k < NN; k++) a2 += L[n * NN + k] * L[k * NN + m];
        g_Ahat[2 * NN * NN + idx] = a2 + eye; // layer 2: L@L + I
    }
}

// One CTA per batch element b. x[b] lives in smem for all 24 (layer,head) pairs.
// Per (l,h): fused GEMM [logits 62x62 | xW 62x64] = x[b](62x512) @ [Walpha | W](512x126),
// then leaky-relu + column softmax (over n), axW = Ahat @ xW, o = a @ axW,
// acc += relu(o); per head: out = relu(acc).
__global__ __launch_bounds__(NTHREADS, 1) void gat_kernel(
    const float* __restrict__ x, const float* __restrict__ Wal,
    const float* __restrict__ Wo, float* __restrict__ out)
{
    extern __shared__ float sm[];
    float* xs   = sm;                 // 64*512  (rows 62,63 zero-padded)
    float* ws   = xs + 64 * CIN;      // KC*128  weight tile [k][col], cols 0..61=Walpha, 64..127=W
    float* att  = ws + KC * 128;      // 62*64   logits -> softmax weights
    float* xw   = att + NN * 64;      // 62*64   x @ W
    float* axw  = xw + NN * 64;       // 62*64   Ahat @ xW
    float* accb = axw + NN * 64;      // 62*64   per-head accumulator over layers
    float* ah   = accb + NN * 64;     // 62*62   Ahat_l staged
    float* dnl  = ah + NN * NN;       // 64      dneg_l staged

    const int b = blockIdx.x;
    const int tid = threadIdx.x;
    const int lane = tid & 31;
    const int warp = tid >> 5;
    const int m0 = lane * 4;   // output col tile base (0..124)
    const int n0 = warp * 4;   // output row tile base (0..60)

    // Load x[b] (62x512 f32) into smem; zero pad rows 62,63.
    {
        const float4* xg4 = (const float4*)(x + (size_t)b * NN * CIN);
        float4* xs4 = (float4*)xs;
        for (int i = tid; i < NN * CIN / 4; i += NTHREADS) xs4[i] = xg4[i];
        for (int i = NN * CIN / 4 + tid; i < 64 * CIN / 4; i += NTHREADS)
            xs4[i] = make_float4(0.f, 0.f, 0.f, 0.f);
    }

    // Weight-tile loader mapping: thread loads fixed column wcol at rows wrow0 + 4j
    const int wcol  = tid & 127;
    const int wrow0 = tid >> 7;  // 0..3
    const bool wvalid = (wcol < NN) || (wcol >= 64);

    for (int h = 0; h < NHEAD; h++) {
        for (int i = tid; i < NN * COUT; i += NTHREADS) accb[i] = 0.f;

        for (int l = 0; l < NLAY; l++) {
            const float* __restrict__ wa = Wal + (size_t)(l * NHEAD + h) * CIN * NN;
            const float* __restrict__ wg = Wo  + (size_t)(l * NHEAD + h) * CIN * COUT;
            const float* __restrict__ wsrc = (wcol < NN) ? (wa + wcol) : (wg + (wcol - 64));
            const int wstride = (wcol < NN) ? NN : COUT;

            float acc[4][4];
            #pragma unroll
            for (int i = 0; i < 4; i++)
                #pragma unroll
                for (int j = 0; j < 4; j++) acc[i][j] = 0.f;

            // software-pipelined weight prefetch (global -> regs -> smem)
            float wreg[8];
            #pragma unroll
            for (int j = 0; j < 8; j++)
                wreg[j] = wvalid ? wsrc[(size_t)(wrow0 + j * 4) * wstride] : 0.f;

            for (int kt = 0; kt < CIN / KC; kt++) {
                __syncthreads();
                #pragma unroll
                for (int j = 0; j < 8; j++) ws[(wrow0 + j * 4) * 128 + wcol] = wreg[j];
                __syncthreads();
                if (kt + 1 < CIN / KC) {
                    int cbase = (kt + 1) * KC + wrow0;
                    #pragma unroll
                    for (int j = 0; j < 8; j++)
                        wreg[j] = wvalid ? wsrc[(size_t)(cbase + j * 4) * wstride] : 0.f;
                }
                const float* xbase = xs + kt * KC;
                #pragma unroll
                for (int k4 = 0; k4 < KC / 4; k4++) {
                    float xr[4][4];
                    #pragma unroll
                    for (int i = 0; i < 4; i++)
                        *(float4*)&xr[i][0] = *(const float4*)(xbase + (n0 + i) * CIN + k4 * 4);
                    #pragma unroll
                    for (int kk = 0; kk < 4; kk++) {
                        float4 wv = *(const float4*)(ws + (k4 * 4 + kk) * 128 + m0);
                        #pragma unroll
                        for (int i = 0; i < 4; i++) {
                            acc[i][0] += xr[i][kk] * wv.x;
                            acc[i][1] += xr[i][kk] * wv.y;
                            acc[i][2] += xr[i][kk] * wv.z;
                            acc[i][3] += xr[i][kk] * wv.w;
                        }
                    }
                }
            }

            // scatter GEMM results: cols [0,62) -> att, cols [64,128) -> xw
            #pragma unroll
            for (int i = 0; i < 4; i++) {
                int n = n0 + i;
                if (n < NN) {
                    #pragma unroll
                    for (int j = 0; j < 4; j++) {
                        int m = m0 + j;
                        if (m < NN) att[n * 64 + m] = acc[i][j];
                        else if (m >= 64) xw[n * 64 + (m - 64)] = acc[i][j];
                    }
                }
            }
            // stage Ahat_l and dneg_l
            for (int i = tid; i < NN * NN; i += NTHREADS) ah[i] = g_Ahat[l * NN * NN + i];
            if (tid < NN) dnl[tid] = g_dneg[l * NN + tid];
            __syncthreads();

            // per-column (over n) leaky-relu + softmax: thread m owns column m
            if (tid < NN) {
                const int m = tid;
                float mx = -1e30f;
                #pragma unroll 1
                for (int n = 0; n < NN; n++) {
                    float v = dnl[n] * att[n * 64 + m];
                    v = (v > 0.f) ? v : 0.01f * v;
                    att[n * 64 + m] = v;
                    mx = fmaxf(mx, v);
                }
                float s = 0.f;
                #pragma unroll 1
                for (int n = 0; n < NN; n++) {
                    float e = __expf(att[n * 64 + m] - mx);
                    att[n * 64 + m] = e;
                    s += e;
                }
                float inv = 1.f / s;
                #pragma unroll 1
                for (int n = 0; n < NN; n++) att[n * 64 + m] *= inv;
            }
            __syncthreads();

            // axw = Ahat @ xw   (62x64, K=62)
            for (int idx = tid; idx < NN * COUT; idx += NTHREADS) {
                int mm = idx >> 6, oo = idx & 63;
                float s = 0.f;
                #pragma unroll 1
                for (int j = 0; j < NN; j++) s += ah[mm * NN + j] * xw[j * 64 + oo];
                axw[idx] = s;
            }
            __syncthreads();

            // o = att @ axw ; accb += relu(o)
            for (int idx = tid; idx < NN * COUT; idx += NTHREADS) {
                int nn = idx >> 6, oo = idx & 63;
                float s = 0.f;
                #pragma unroll 1
                for (int m = 0; m < NN; m++) s += att[nn * 64 + m] * axw[m * 64 + oo];
                accb[idx] += fmaxf(s, 0.f);
            }
            // next layer's first __syncthreads (before ws store) orders att/xw reuse
        }

        // store this head's output slice: out[b][n][h*64 + o]
        float* outh = out + (size_t)b * NN * (NHEAD * COUT) + h * COUT;
        for (int idx = tid; idx < NN * COUT; idx += NTHREADS) {
            int nn = idx >> 6, oo = idx & 63;
            outh[(size_t)nn * (NHEAD * COUT) + oo] = fmaxf(accb[idx], 0.f);
        }
    }
}

extern "C" void kernel_launch(void* const* d_in, const int* in_sizes, int n_in,
                              void* d_out, int out_size) {
    const float* x   = (const float*)d_in[0];
    const float* L   = (const float*)d_in[1];
    const float* Wal = (const float*)d_in[2];
    const float* W   = (const float*)d_in[3];
    float* out = (float*)d_out;

    size_t smem = (size_t)(64 * CIN + KC * 128 + 4 * NN * 64 + NN * NN + 64) * sizeof(float);
    cudaFuncSetAttribute(gat_kernel, cudaFuncAttributeMaxDynamicSharedMemorySize, (int)smem);

    precompute_kernel<<<1, 256>>>(L);
    gat_kernel<<<NBATCH, NTHREADS, smem>>>(x, Wal, W, out);
}

// round 2
// speedup vs baseline: 1.0004x; 1.0004x over previous
#include <cuda_runtime.h>

#define NBATCH 2048
#define NN 62
#define CIN 512
#define NLAY 3
#define NHEAD 8
#define COUT 64
#define NTHREADS 512
#define KC 32

// Precomputed adjacency data: A_hat_l = A_l + I, dneg_l[n] = 1/rowsum(A_l)
__device__ float g_Ahat[NLAY * NN * NN];
__device__ float g_dneg[NLAY * NN];

__global__ void precompute_kernel(const float* __restrict__ L) {
    __shared__ float D1s[NN];
    int tid = threadIdx.x;
    if (tid < NN) {
        float s = 0.f;
        for (int m = 0; m < NN; m++) s += L[tid * NN + m];
        D1s[tid] = s;
    }
    __syncthreads();
    if (tid < NN) {
        g_dneg[tid] = 1.0f;  // layer 0: A = I, D = 1
        float d1 = D1s[tid];
        g_dneg[NN + tid] = (d1 == 0.f) ? 0.f : (1.f / d1);
        // D2[n] = rowsum(L@L)[n] = sum_k L[n,k] * rowsumL[k]
        float d2 = 0.f;
        for (int k = 0; k < NN; k++) d2 += L[tid * NN + k] * D1s[k];
        g_dneg[2 * NN + tid] = (d2 == 0.f) ? 0.f : (1.f / d2);
    }
    for (int idx = tid; idx < NN * NN; idx += blockDim.x) {
        int n = idx / NN, m = idx - n * NN;
        float eye = (n == m) ? 1.f : 0.f;
        g_Ahat[idx] = 2.f * eye;             // layer 0: I + I
        g_Ahat[NN * NN + idx] = L[idx] + eye; // layer 1: L + I
        float a2 = 0.f;
        for (int k = 0; k < NN; k++) a2 += L[n * NN + k] * L[k * NN + m];
        g_Ahat[2 * NN * NN + idx] = a2 + eye; // layer 2: L@L + I
    }
}

// One CTA per batch element b. x[b] lives in smem for all 24 (layer,head) pairs.
// Per (l,h): fused GEMM [logits 62x62 | xW 62x64] = x[b](62x512) @ [Walpha | W](512x126),
// then leaky-relu + column softmax (over n), axW = Ahat @ xW, o = a @ axW,
// acc += relu(o); per head: out = relu(acc).
__global__ __launch_bounds__(NTHREADS, 1) void gat_kernel(
    const float* __restrict__ x, const float* __restrict__ Wal,
    const float* __restrict__ Wo, float* __restrict__ out)
{
    extern __shared__ float sm[];
    float* xs   = sm;                 // 64*512  (rows 62,63 zero-padded)
    float* ws   = xs + 64 * CIN;      // KC*128  weight tile [k][col], cols 0..61=Walpha, 64..127=W
    float* att  = ws + KC * 128;      // 62*64   logits -> softmax weights
    float* xw   = att + NN * 64;      // 62*64   x @ W
    float* axw  = xw + NN * 64;       // 62*64   Ahat @ xW
    float* accb = axw + NN * 64;      // 62*64   per-head accumulator over layers
    float* ah   = accb + NN * 64;     // 62*62   Ahat_l staged
    float* dnl  = ah + NN * NN;       // 64      dneg_l staged

    const int b = blockIdx.x;
    const int tid = threadIdx.x;
    const int lane = tid & 31;
    const int warp = tid >> 5;
    const int m0 = lane * 4;   // output col tile base (0..124)
    const int n0 = warp * 4;   // output row tile base (0..60)

    // Load x[b] (62x512 f32) into smem; zero pad rows 62,63.
    {
        const float4* xg4 = (const float4*)(x + (size_t)b * NN * CIN);
        float4* xs4 = (float4*)xs;
        for (int i = tid; i < NN * CIN / 4; i += NTHREADS) xs4[i] = xg4[i];
        for (int i = NN * CIN / 4 + tid; i < 64 * CIN / 4; i += NTHREADS)
            xs4[i] = make_float4(0.f, 0.f, 0.f, 0.f);
    }

    // Weight-tile loader mapping: thread loads fixed column wcol at rows wrow0 + 4j
    const int wcol  = tid & 127;
    const int wrow0 = tid >> 7;  // 0..3
    const bool wvalid = (wcol < NN) || (wcol >= 64);

    for (int h = 0; h < NHEAD; h++) {
        for (int i = tid; i < NN * COUT; i += NTHREADS) accb[i] = 0.f;

        for (int l = 0; l < NLAY; l++) {
            const float* __restrict__ wa = Wal + (size_t)(l * NHEAD + h) * CIN * NN;
            const float* __restrict__ wg = Wo  + (size_t)(l * NHEAD + h) * CIN * COUT;
            const float* __restrict__ wsrc = (wcol < NN) ? (wa + wcol) : (wg + (wcol - 64));
            const int wstride = (wcol < NN) ? NN : COUT;

            float acc[4][4];
            #pragma unroll
            for (int i = 0; i < 4; i++)
                #pragma unroll
                for (int j = 0; j < 4; j++) acc[i][j] = 0.f;

            // software-pipelined weight prefetch (global -> regs -> smem)
            float wreg[8];
            #pragma unroll
            for (int j = 0; j < 8; j++)
                wreg[j] = wvalid ? wsrc[(size_t)(wrow0 + j * 4) * wstride] : 0.f;

            for (int kt = 0; kt < CIN / KC; kt++) {
                __syncthreads();
                #pragma unroll
                for (int j = 0; j < 8; j++) ws[(wrow0 + j * 4) * 128 + wcol] = wreg[j];
                __syncthreads();
                if (kt + 1 < CIN / KC) {
                    int cbase = (kt + 1) * KC + wrow0;
                    #pragma unroll
                    for (int j = 0; j < 8; j++)
                        wreg[j] = wvalid ? wsrc[(size_t)(cbase + j * 4) * wstride] : 0.f;
                }
                const float* xbase = xs + kt * KC;
                #pragma unroll
                for (int k4 = 0; k4 < KC / 4; k4++) {
                    float xr[4][4];
                    #pragma unroll
                    for (int i = 0; i < 4; i++)
                        *(float4*)&xr[i][0] = *(const float4*)(xbase + (n0 + i) * CIN + k4 * 4);
                    #pragma unroll
                    for (int kk = 0; kk < 4; kk++) {
                        float4 wv = *(const float4*)(ws + (k4 * 4 + kk) * 128 + m0);
                        #pragma unroll
                        for (int i = 0; i < 4; i++) {
                            acc[i][0] += xr[i][kk] * wv.x;
                            acc[i][1] += xr[i][kk] * wv.y;
                            acc[i][2] += xr[i][kk] * wv.z;
                            acc[i][3] += xr[i][kk] * wv.w;
                        }
                    }
                }
            }

            // scatter GEMM results: cols [0,62) -> att, cols [64,128) -> xw
            #pragma unroll
            for (int i = 0; i < 4; i++) {
                int n = n0 + i;
                if (n < NN) {
                    #pragma unroll
                    for (int j = 0; j < 4; j++) {
                        int m = m0 + j;
                        if (m < NN) att[n * 64 + m] = acc[i][j];
                        else if (m >= 64) xw[n * 64 + (m - 64)] = acc[i][j];
                    }
                }
            }
            // stage Ahat_l and dneg_l
            for (int i = tid; i < NN * NN; i += NTHREADS) ah[i] = g_Ahat[l * NN * NN + i];
            if (tid < NN) dnl[tid] = g_dneg[l * NN + tid];
            __syncthreads();

            // per-column (over n) leaky-relu + softmax: thread m owns column m
            if (tid < NN) {
                const int m = tid;
                float mx = -1e30f;
                #pragma unroll 1
                for (int n = 0; n < NN; n++) {
                    float v = dnl[n] * att[n * 64 + m];
                    v = (v > 0.f) ? v : 0.01f * v;
                    att[n * 64 + m] = v;
                    mx = fmaxf(mx, v);
                }
                float s = 0.f;
                #pragma unroll 1
                for (int n = 0; n < NN; n++) {
                    float e = __expf(att[n * 64 + m] - mx);
                    att[n * 64 + m] = e;
                    s += e;
                }
                float inv = 1.f / s;
                #pragma unroll 1
                for (int n = 0; n < NN; n++) att[n * 64 + m] *= inv;
            }
            __syncthreads();

            // axw = Ahat @ xw   (62x64, K=62)
            for (int idx = tid; idx < NN * COUT; idx += NTHREADS) {
                int mm = idx >> 6, oo = idx & 63;
                float s = 0.f;
                #pragma unroll 1
                for (int j = 0; j < NN; j++) s += ah[mm * NN + j] * xw[j * 64 + oo];
                axw[idx] = s;
            }
            __syncthreads();

            // o = att @ axw ; accb += relu(o)
            for (int idx = tid; idx < NN * COUT; idx += NTHREADS) {
                int nn = idx >> 6, oo = idx & 63;
                float s = 0.f;
                #pragma unroll 1
                for (int m = 0; m < NN; m++) s += att[nn * 64 + m] * axw[m * 64 + oo];
                accb[idx] += fmaxf(s, 0.f);
            }
            // next layer's first __syncthreads (before ws store) orders att/xw reuse
        }

        // store this head's output slice: out[b][n][h*64 + o]
        float* outh = out + (size_t)b * NN * (NHEAD * COUT) + h * COUT;
        for (int idx = tid; idx < NN * COUT; idx += NTHREADS) {
            int nn = idx >> 6, oo = idx & 63;
            outh[(size_t)nn * (NHEAD * COUT) + oo] = fmaxf(accb[idx], 0.f);
        }
    }
}

extern "C" void kernel_launch(void* const* d_in, const int* in_sizes, int n_in,
                              void* d_out, int out_size) {
    const float* x   = (const float*)d_in[0];
    const float* L   = (const float*)d_in[1];
    const float* Wal = (const float*)d_in[2];
    const float* W   = (const float*)d_in[3];
    float* out = (float*)d_out;

    size_t smem = (size_t)(64 * CIN + KC * 128 + 4 * NN * 64 + NN * NN + 64) * sizeof(float);
    cudaFuncSetAttribute(gat_kernel, cudaFuncAttributeMaxDynamicSharedMemorySize, (int)smem);

    precompute_kernel<<<1, 256>>>(L);
    gat_kernel<<<NBATCH, NTHREADS, smem>>>(x, Wal, W, out);
}

// round 5
// speedup vs baseline: 1.6997x; 1.6989x over previous
#include <cuda_runtime.h>
#include <cuda_bf16.h>
#include <mma.h>
#include <cstdint>
#include <cstddef>

using namespace nvcuda;

#define NN 62
#define CIN 512
#define NLAY 3
#define NHEAD 8
#define CO 64
#define NB 2048
#define NTH 512
#define PIT 68
#define HSTR (128 * PIT)

// ---------------- device global scratch ----------------
__device__ __nv_bfloat16 g_xh[(size_t)NB * NN * CIN];
__device__ __nv_bfloat16 g_xl[(size_t)NB * NN * CIN];
__device__ __nv_bfloat16 g_Bh[NLAY * 4 * 256 * CIN];
__device__ __nv_bfloat16 g_Bl[NLAY * 4 * 256 * CIN];
__device__ float g_Ahat[NLAY * NN * NN];
__device__ float g_dneg[NLAY * NN];

// ---------------- helpers ----------------
__device__ __forceinline__ uint32_t smem_u32(const void* p) {
    uint32_t a;
    asm("{ .reg .u64 t; cvta.to.shared.u64 t, %1; cvt.u32.u64 %0, t; }" : "=r"(a) : "l"(p));
    return a;
}
#define CP_ASYNC16(dst, src) \
    asm volatile("cp.async.cg.shared.global [%0], [%1], 16;" :: "r"(dst), "l"(src) : "memory")
#define CP_COMMIT() asm volatile("cp.async.commit_group;" ::: "memory")
#define CP_WAIT(n)  asm volatile("cp.async.wait_group %0;" :: "n"(n) : "memory")

// ---------------- precompute kernels ----------------
__global__ void conv_x(const float* __restrict__ x) {
    size_t n8 = (size_t)NB * NN * CIN / 8;
    for (size_t i = blockIdx.x * (size_t)blockDim.x + threadIdx.x; i < n8;
         i += (size_t)gridDim.x * blockDim.x) {
        const float4* s = (const float4*)x + i * 2;
        float4 v0 = s[0], v1 = s[1];
        float f[8] = {v0.x, v0.y, v0.z, v0.w, v1.x, v1.y, v1.z, v1.w};
        alignas(16) __nv_bfloat16 h[8], lo[8];
        #pragma unroll
        for (int j = 0; j < 8; j++) {
            h[j] = __float2bfloat16(f[j]);
            lo[j] = __float2bfloat16(f[j] - __bfloat162float(h[j]));
        }
        *(uint4*)(g_xh + i * 8) = *(const uint4*)h;
        *(uint4*)(g_xl + i * 8) = *(const uint4*)lo;
    }
}
// g_B[pass=l*4+ph][n'=hloc*128+c][k]: c<62 -> Walpha, 64..127 -> W, else 0
__global__ void conv_w(const float* __restrict__ Wal, const float* __restrict__ Wo) {
    int total = NLAY * 4 * 256 * CIN;
    for (int i = blockIdx.x * blockDim.x + threadIdx.x; i < total; i += gridDim.x * blockDim.x) {
        int k = i & 511;
        int t = i >> 9;
        int n = t & 255;
        int lp = t >> 8;
        int l = lp >> 2;
        int head = (lp & 3) * 2 + (n >> 7);
        int c = n & 127;
        float v = 0.f;
        if (c < NN) v = Wal[((size_t)(l * NHEAD + head) * CIN + k) * NN + c];
        else if (c >= 64) v = Wo[((size_t)(l * NHEAD + head) * CIN + k) * CO + (c - 64)];
        __nv_bfloat16 h = __float2bfloat16(v);
        g_Bh[i] = h;
        g_Bl[i] = __float2bfloat16(v - __bfloat162float(h));
    }
}
__global__ void precompute_adj(const float* __restrict__ L) {
    __shared__ float D1s[NN];
    int tid = threadIdx.x;
    if (tid < NN) {
        float s = 0.f;
        for (int m = 0; m < NN; m++) s += L[tid * NN + m];
        D1s[tid] = s;
    }
    __syncthreads();
    if (tid < NN) {
        g_dneg[tid] = 1.0f;
        float d1 = D1s[tid];
        g_dneg[NN + tid] = (d1 == 0.f) ? 0.f : (1.f / d1);
        float d2 = 0.f;
        for (int k = 0; k < NN; k++) d2 += L[tid * NN + k] * D1s[k];
        g_dneg[2 * NN + tid] = (d2 == 0.f) ? 0.f : (1.f / d2);
    }
    for (int idx = tid; idx < NN * NN; idx += blockDim.x) {
        int n = idx / NN, m = idx - n * NN;
        float eye = (n == m) ? 1.f : 0.f;
        g_Ahat[idx] = 2.f * eye;
        g_Ahat[NN * NN + idx] = L[idx] + eye;
        float a2 = 0.f;
        for (int k = 0; k < NN; k++) a2 += L[n * NN + k] * L[k * NN + m];
        g_Ahat[2 * NN * NN + idx] = a2 + eye;
    }
}

// ---------------- main kernel ----------------
// smem overlays (bytes):
//  MMA phase:  A(buf,plane) = buf*32768 + plane*16384          [0,65536)
//              B(buf,plane) = 65536 + buf*65536 + plane*32768  [65536,196608)
//  EPI phase:  dnl@0  ahm@256  lg@15872  xw@85504  axw@155136  (end 224768)
#define SMEM_BYTES 224768

__global__ __launch_bounds__(NTH, 1) void gat_wmma(float* __restrict__ out) {
    extern __shared__ char smc[];
    const uint32_t smb = smem_u32(smc);
    const int tid = threadIdx.x;
    const int warp = tid >> 5;
    const int b2 = blockIdx.x * 2;

    float* dnl = (float*)(smc + 0);
    float* ahm = (float*)(smc + 256);
    float* lg  = (float*)(smc + 15872);
    float* xw  = (float*)(smc + 85504);
    float* axw = (float*)(smc + 155136);

    // warp tile mapping: 8 M-tiles x 16 N-tiles of 16x16; warp owns 2x4
    const int mtb = (warp >> 2) * 2;
    const int ntb = (warp & 3) * 4;

    for (int pass = 0; pass < 12; pass++) {
        const int l = pass >> 2, ph = pass & 3;

        // ---- zero A padding rows (62,63,126,127) for both bufs/planes ----
        if (tid < 256) {
            int buf = (tid >> 7) & 1, p = (tid >> 6) & 1, r = (tid >> 3) & 7, seg = tid & 7;
            int row = (r >> 1) * 64 + 62 + (r & 1);
            *(uint4*)(smc + buf * 32768 + p * 16384 + row * 128 + seg * 16) =
                make_uint4(0, 0, 0, 0);
        }

        wmma::fragment<wmma::accumulator, 16, 16, 16, float> c[2][4];
        #pragma unroll
        for (int i = 0; i < 2; i++)
            #pragma unroll
            for (int j = 0; j < 4; j++) wmma::fill_fragment(c[i][j], 0.f);

        // ---- issue loads for kt=0 into buf 0 ----
        {
            const int kt = 0, buf = 0;
            const uint32_t ab = smb + buf * 32768;
            for (int u = tid; u < 2048; u += NTH) {
                int p = u >> 10, idx = u & 1023;
                int row = idx >> 3, seg = idx & 7;
                int nn = row & 63;
                if (nn < NN) {
                    const __nv_bfloat16* src = (p ? g_xl : g_xh) +
                        ((size_t)(b2 + (row >> 6)) * NN + nn) * CIN + kt * 64 + seg * 8;
                    CP_ASYNC16(ab + p * 16384 + row * 128 + seg * 16, src);
                }
            }
            const uint32_t bb = smb + 65536 + buf * 65536;
            for (int u = tid; u < 4096; u += NTH) {
                int p = u >> 11, idx = u & 2047;
                int row = idx >> 3, seg = idx & 7;
                const __nv_bfloat16* src = (p ? g_Bl : g_Bh) +
                    ((size_t)pass * 256 + row) * CIN + kt * 64 + seg * 8;
                CP_ASYNC16(bb + p * 32768 + row * 128 + seg * 16, src);
            }
            CP_COMMIT();
        }

        // ---- K loop: 8 chunks of 64, double buffered ----
        for (int kt = 0; kt < 8; kt++) {
            const int buf = kt & 1;
            if (kt < 7) {
                const int nbuf = buf ^ 1;
                const uint32_t ab = smb + nbuf * 32768;
                for (int u = tid; u < 2048; u += NTH) {
                    int p = u >> 10, idx = u & 1023;
                    int row = idx >> 3, seg = idx & 7;
                    int nn = row & 63;
                    if (nn < NN) {
                        const __nv_bfloat16* src = (p ? g_xl : g_xh) +
                            ((size_t)(b2 + (row >> 6)) * NN + nn) * CIN + (kt + 1) * 64 + seg * 8;
                        CP_ASYNC16(ab + p * 16384 + row * 128 + seg * 16, src);
                    }
                }
                const uint32_t bb = smb + 65536 + nbuf * 65536;
                for (int u = tid; u < 4096; u += NTH) {
                    int p = u >> 11, idx = u & 2047;
                    int row = idx >> 3, seg = idx & 7;
                    const __nv_bfloat16* src = (p ? g_Bl : g_Bh) +
                        ((size_t)pass * 256 + row) * CIN + (kt + 1) * 64 + seg * 8;
                    CP_ASYNC16(bb + p * 32768 + row * 128 + seg * 16, src);
                }
                CP_COMMIT();
                CP_WAIT(1);
            } else {
                CP_WAIT(0);
            }
            __syncthreads();

            // compute on buf: 3 split terms (Ah*Bh + Ah*Bl + Al*Bh)
            #pragma unroll
            for (int t = 0; t < 3; t++) {
                const __nv_bfloat16* As = (const __nv_bfloat16*)(smc + buf * 32768 +
                                                                 (t == 2 ? 16384 : 0));
                const __nv_bfloat16* Bs = (const __nv_bfloat16*)(smc + 65536 + buf * 65536 +
                                                                 (t == 1 ? 32768 : 0));
                #pragma unroll
                for (int k16 = 0; k16 < 4; k16++) {
                    wmma::fragment<wmma::matrix_a, 16, 16, 16, __nv_bfloat16, wmma::row_major> a[2];
                    #pragma unroll
                    for (int i = 0; i < 2; i++)
                        wmma::load_matrix_sync(a[i], As + (mtb + i) * 16 * 64 + k16 * 16, 64);
                    #pragma unroll
                    for (int j = 0; j < 4; j++) {
                        wmma::fragment<wmma::matrix_b, 16, 16, 16, __nv_bfloat16, wmma::col_major> b;
                        wmma::load_matrix_sync(b, Bs + (ntb + j) * 16 * 64 + k16 * 16, 64);
                        wmma::mma_sync(c[0][j], a[0], b, c[0][j]);
                        wmma::mma_sync(c[1][j], a[1], b, c[1][j]);
                    }
                }
            }
            __syncthreads();
        }

        // ---- store C tiles into lg / xw ----
        #pragma unroll
        for (int i = 0; i < 2; i++)
            #pragma unroll
            for (int j = 0; j < 4; j++) {
                int mt = mtb + i, nt = ntb + j;
                int head = nt >> 3, ccb = (nt & 7) * 16;
                float* dst = (ccb < 64 ? lg + head * HSTR + ccb
                                       : xw + head * HSTR + (ccb - 64)) + mt * 16 * PIT;
                wmma::store_matrix_sync(dst, c[i][j], PIT, wmma::mem_row_major);
            }
        // stage dneg + Ahat
        if (tid < NN) dnl[tid] = g_dneg[l * NN + tid];
        if (l > 0)
            for (int i = tid; i < NN * NN; i += NTH) ahm[i] = g_Ahat[l * NN * NN + i];
        __syncthreads();

        // ---- column softmax (head, batch, column m; over n) ----
        if (tid < 2 * 2 * NN) {
            int head = tid / (2 * NN);
            int rr = tid - head * 2 * NN;
            int batch = rr / NN, m = rr - batch * NN;
            float* col = lg + head * HSTR + batch * 64 * PIT + m;
            float mx = -1e30f;
            #pragma unroll 1
            for (int n = 0; n < NN; n++) {
                float v = dnl[n] * col[n * PIT];
                v = (v > 0.f) ? v : 0.01f * v;
                col[n * PIT] = v;
                mx = fmaxf(mx, v);
            }
            float ssum = 0.f;
            #pragma unroll 1
            for (int n = 0; n < NN; n++) {
                float e = __expf(col[n * PIT] - mx);
                col[n * PIT] = e;
                ssum += e;
            }
            float inv = 1.f / ssum;
            #pragma unroll 1
            for (int n = 0; n < NN; n++) col[n * PIT] *= inv;
        }

        // ---- axw = Ahat @ xw (layer 0: 2*xw) ----
        const int g2 = tid >> 8, tile = tid & 255;
        const int m0 = (tile >> 4) * 4, o0 = (tile & 15) * 4;
        if (l == 0) {
            for (int i = tid; i < 2 * 128 * 64; i += NTH) {
                int head = i >> 13, rem = i & 8191;
                int row = rem >> 6, o = rem & 63;
                axw[head * HSTR + row * PIT + o] = 2.f * xw[head * HSTR + row * PIT + o];
            }
        } else {
            for (int gi = 0; gi < 2; gi++) {
                int grp = gi * 2 + g2;
                int head = grp >> 1, batch = grp & 1;
                const float* xb = xw + head * HSTR + batch * 64 * PIT;
                float acc[4][4];
                #pragma unroll
                for (int i = 0; i < 4; i++)
                    #pragma unroll
                    for (int j = 0; j < 4; j++) acc[i][j] = 0.f;
                #pragma unroll 2
                for (int j = 0; j < NN; j++) {
                    float av[4], wv[4];
                    #pragma unroll
                    for (int i = 0; i < 4; i++)
                        av[i] = (m0 + i < NN) ? ahm[(m0 + i) * NN + j] : 0.f;
                    #pragma unroll
                    for (int jj = 0; jj < 4; jj++) wv[jj] = xb[j * PIT + o0 + jj];
                    #pragma unroll
                    for (int i = 0; i < 4; i++)
                        #pragma unroll
                        for (int jj = 0; jj < 4; jj++) acc[i][jj] += av[i] * wv[jj];
                }
                float* ab = axw + head * HSTR + batch * 64 * PIT;
                #pragma unroll
                for (int i = 0; i < 4; i++)
                    if (m0 + i < NN)
                        #pragma unroll
                        for (int jj = 0; jj < 4; jj++)
                            ab[(m0 + i) * PIT + o0 + jj] = acc[i][jj];
            }
        }
        __syncthreads();

        // ---- o = att @ axw ; out RMW ----
        for (int gi = 0; gi < 2; gi++) {
            int grp = gi * 2 + g2;
            int head = grp >> 1, batch = grp & 1;
            const float* ab = lg + head * HSTR + batch * 64 * PIT;
            const float* wb = axw + head * HSTR + batch * 64 * PIT;
            float acc[4][4];
            #pragma unroll
            for (int i = 0; i < 4; i++)
                #pragma unroll
                for (int j = 0; j < 4; j++) acc[i][j] = 0.f;
            #pragma unroll 2
            for (int m = 0; m < NN; m++) {
                float av[4], wv[4];
                #pragma unroll
                for (int i = 0; i < 4; i++) av[i] = ab[(m0 + i) * PIT + m];
                #pragma unroll
                for (int jj = 0; jj < 4; jj++) wv[jj] = wb[m * PIT + o0 + jj];
                #pragma unroll
                for (int i = 0; i < 4; i++)
                    #pragma unroll
                    for (int jj = 0; jj < 4; jj++) acc[i][jj] += av[i] * wv[jj];
            }
            int hg = ph * 2 + head;
            #pragma unroll
            for (int i = 0; i < 4; i++) {
                int n = m0 + i;
                if (n < NN) {
                    float4 add;
                    add.x = fmaxf(acc[i][0], 0.f);
                    add.y = fmaxf(acc[i][1], 0.f);
                    add.z = fmaxf(acc[i][2], 0.f);
                    add.w = fmaxf(acc[i][3], 0.f);
                    float4* op = (float4*)(out + ((size_t)(b2 + batch) * NN + n) * 512 + hg * 64 + o0);
                    if (pass < 4) {
                        *op = add;
                    } else if (pass < 8) {
                        float4 o4 = *op;
                        o4.x += add.x; o4.y += add.y; o4.z += add.z; o4.w += add.w;
                        *op = o4;
                    } else {
                        float4 o4 = *op;
                        o4.x = fmaxf(o4.x + add.x, 0.f);
                        o4.y = fmaxf(o4.y + add.y, 0.f);
                        o4.z = fmaxf(o4.z + add.z, 0.f);
                        o4.w = fmaxf(o4.w + add.w, 0.f);
                        *op = o4;
                    }
                }
            }
        }
        __syncthreads();
    }
}

extern "C" void kernel_launch(void* const* d_in, const int* in_sizes, int n_in,
                              void* d_out, int out_size) {
    const float* x   = (const float*)d_in[0];
    const float* L   = (const float*)d_in[1];
    const float* Wal = (const float*)d_in[2];
    const float* W   = (const float*)d_in[3];
    float* out = (float*)d_out;

    cudaFuncSetAttribute(gat_wmma, cudaFuncAttributeMaxDynamicSharedMemorySize, SMEM_BYTES);
    conv_x<<<8192, 256>>>(x);
    conv_w<<<3072, 256>>>(Wal, W);
    precompute_adj<<<1, 256>>>(L);
    gat_wmma<<<NB / 2, NTH, SMEM_BYTES>>>(out);
}

// round 6
// speedup vs baseline: 4.6345x; 2.7267x over previous
#include <cuda_runtime.h>
#include <cuda_bf16.h>
#include <mma.h>
#include <cstdint>
#include <cstddef>

using namespace nvcuda;

#define NN 62
#define CIN 512
#define NLAY 3
#define NHEAD 8
#define CO 64
#define NB 2048
#define NTH 512
#define PIT 68
#define HSTR (128 * PIT)
#define APIT 144              // A/B smem row pitch in bytes (72 bf16) — conflict-free ldmatrix
#define APITE 72              // pitch in elements

// ---------------- device global scratch ----------------
__device__ __nv_bfloat16 g_xh[(size_t)NB * NN * CIN];
__device__ __nv_bfloat16 g_xl[(size_t)NB * NN * CIN];
__device__ __nv_bfloat16 g_Bh[NLAY * 4 * 256 * CIN];
__device__ __nv_bfloat16 g_Bl[NLAY * 4 * 256 * CIN];
__device__ float g_Ahat[NLAY * NN * NN];
__device__ float g_dneg[NLAY * NN];

// ---------------- helpers ----------------
__device__ __forceinline__ uint32_t smem_u32(const void* p) {
    uint32_t a;
    asm("{ .reg .u64 t; cvta.to.shared.u64 t, %1; cvt.u32.u64 %0, t; }" : "=r"(a) : "l"(p));
    return a;
}
#define CP_ASYNC16(dst, src) \
    asm volatile("cp.async.cg.shared.global [%0], [%1], 16;" :: "r"(dst), "l"(src) : "memory")
#define CP_COMMIT() asm volatile("cp.async.commit_group;" ::: "memory")
#define CP_WAIT(n)  asm volatile("cp.async.wait_group %0;" :: "n"(n) : "memory")

// ---------------- precompute kernels ----------------
__global__ void conv_x(const float* __restrict__ x) {
    size_t n8 = (size_t)NB * NN * CIN / 8;
    for (size_t i = blockIdx.x * (size_t)blockDim.x + threadIdx.x; i < n8;
         i += (size_t)gridDim.x * blockDim.x) {
        const float4* s = (const float4*)x + i * 2;
        float4 v0 = s[0], v1 = s[1];
        float f[8] = {v0.x, v0.y, v0.z, v0.w, v1.x, v1.y, v1.z, v1.w};
        alignas(16) __nv_bfloat16 h[8], lo[8];
        #pragma unroll
        for (int j = 0; j < 8; j++) {
            h[j] = __float2bfloat16(f[j]);
            lo[j] = __float2bfloat16(f[j] - __bfloat162float(h[j]));
        }
        *(uint4*)(g_xh + i * 8) = *(const uint4*)h;
        *(uint4*)(g_xl + i * 8) = *(const uint4*)lo;
    }
}
// g_B[pass=l*4+ph][n'=hloc*128+c][k]: c<62 -> Walpha, 64..127 -> W, else 0
__global__ void conv_w(const float* __restrict__ Wal, const float* __restrict__ Wo) {
    int total = NLAY * 4 * 256 * CIN;
    for (int i = blockIdx.x * blockDim.x + threadIdx.x; i < total; i += gridDim.x * blockDim.x) {
        int k = i & 511;
        int t = i >> 9;
        int n = t & 255;
        int lp = t >> 8;
        int l = lp >> 2;
        int head = (lp & 3) * 2 + (n >> 7);
        int c = n & 127;
        float v = 0.f;
        if (c < NN) v = Wal[((size_t)(l * NHEAD + head) * CIN + k) * NN + c];
        else if (c >= 64) v = Wo[((size_t)(l * NHEAD + head) * CIN + k) * CO + (c - 64)];
        __nv_bfloat16 h = __float2bfloat16(v);
        g_Bh[i] = h;
        g_Bl[i] = __float2bfloat16(v - __bfloat162float(h));
    }
}
__global__ void precompute_adj(const float* __restrict__ L) {
    __shared__ float D1s[NN];
    int tid = threadIdx.x;
    if (tid < NN) {
        float s = 0.f;
        for (int m = 0; m < NN; m++) s += L[tid * NN + m];
        D1s[tid] = s;
    }
    __syncthreads();
    if (tid < NN) {
        g_dneg[tid] = 1.0f;
        float d1 = D1s[tid];
        g_dneg[NN + tid] = (d1 == 0.f) ? 0.f : (1.f / d1);
        float d2 = 0.f;
        for (int k = 0; k < NN; k++) d2 += L[tid * NN + k] * D1s[k];
        g_dneg[2 * NN + tid] = (d2 == 0.f) ? 0.f : (1.f / d2);
    }
    for (int idx = tid; idx < NN * NN; idx += blockDim.x) {
        int n = idx / NN, m = idx - n * NN;
        float eye = (n == m) ? 1.f : 0.f;
        g_Ahat[idx] = 2.f * eye;
        g_Ahat[NN * NN + idx] = L[idx] + eye;
        float a2 = 0.f;
        for (int k = 0; k < NN; k++) a2 += L[n * NN + k] * L[k * NN + m];
        g_Ahat[2 * NN * NN + idx] = a2 + eye;
    }
}

// ---------------- main kernel ----------------
// smem overlays (bytes):
//  MMA phase:  A(buf,plane) = buf*36864 + plane*18432            [0,73728)
//              B(buf,plane) = 73728 + buf*73728 + plane*36864    [73728,221184)
//  EPI phase:  dnl@0  ahm@256  lg@15872  xw@85504  axw@155136  (end 224768)
#define SMEM_BYTES 224768

__global__ __launch_bounds__(NTH, 1) void gat_wmma(float* __restrict__ out) {
    extern __shared__ char smc[];
    const uint32_t smb = smem_u32(smc);
    const int tid = threadIdx.x;
    const int warp = tid >> 5;
    const int b2 = blockIdx.x * 2;

    float* dnl = (float*)(smc + 0);
    float* ahm = (float*)(smc + 256);
    float* lg  = (float*)(smc + 15872);
    float* xw  = (float*)(smc + 85504);
    float* axw = (float*)(smc + 155136);

    // warp tile mapping: 8 M-tiles x 16 N-tiles of 16x16; warp owns 2x4
    const int mtb = (warp >> 2) * 2;
    const int ntb = (warp & 3) * 4;

    for (int pass = 0; pass < 12; pass++) {
        const int l = pass >> 2, ph = pass & 3;

        // ---- zero A padding rows (62,63,126,127), both planes/bufs ----
        if (tid < 128) {
            int buf = (tid >> 6) & 1, p = (tid >> 5) & 1, r = (tid >> 3) & 3, seg = tid & 7;
            int row = (r >> 1) * 64 + 62 + (r & 1);
            *(uint4*)(smc + buf * 36864 + p * 18432 + row * APIT + seg * 16) =
                make_uint4(0, 0, 0, 0);
        }

        wmma::fragment<wmma::accumulator, 16, 16, 16, float> c[2][4];
        #pragma unroll
        for (int i = 0; i < 2; i++)
            #pragma unroll
            for (int j = 0; j < 4; j++) wmma::fill_fragment(c[i][j], 0.f);

        // ---- issue loads for kt=0 into buf 0 ----
        {
            const int kt = 0, buf = 0;
            const uint32_t ab = smb + buf * 36864;
            for (int u = tid; u < 2048; u += NTH) {
                int p = u >> 10, idx = u & 1023;
                int row = idx >> 3, seg = idx & 7;
                int nn = row & 63;
                if (nn < NN) {
                    const __nv_bfloat16* src = (p ? g_xl : g_xh) +
                        ((size_t)(b2 + (row >> 6)) * NN + nn) * CIN + kt * 64 + seg * 8;
                    CP_ASYNC16(ab + p * 18432 + row * APIT + seg * 16, src);
                }
            }
            const uint32_t bb = smb + 73728 + buf * 73728;
            for (int u = tid; u < 4096; u += NTH) {
                int p = u >> 11, idx = u & 2047;
                int row = idx >> 3, seg = idx & 7;
                const __nv_bfloat16* src = (p ? g_Bl : g_Bh) +
                    ((size_t)pass * 256 + row) * CIN + kt * 64 + seg * 8;
                CP_ASYNC16(bb + p * 36864 + row * APIT + seg * 16, src);
            }
            CP_COMMIT();
        }

        // ---- K loop: 8 chunks of 64, double buffered ----
        for (int kt = 0; kt < 8; kt++) {
            const int buf = kt & 1;
            if (kt < 7) {
                const int nbuf = buf ^ 1;
                const uint32_t ab = smb + nbuf * 36864;
                for (int u = tid; u < 2048; u += NTH) {
                    int p = u >> 10, idx = u & 1023;
                    int row = idx >> 3, seg = idx & 7;
                    int nn = row & 63;
                    if (nn < NN) {
                        const __nv_bfloat16* src = (p ? g_xl : g_xh) +
                            ((size_t)(b2 + (row >> 6)) * NN + nn) * CIN + (kt + 1) * 64 + seg * 8;
                        CP_ASYNC16(ab + p * 18432 + row * APIT + seg * 16, src);
                    }
                }
                const uint32_t bb = smb + 73728 + nbuf * 73728;
                for (int u = tid; u < 4096; u += NTH) {
                    int p = u >> 11, idx = u & 2047;
                    int row = idx >> 3, seg = idx & 7;
                    const __nv_bfloat16* src = (p ? g_Bl : g_Bh) +
                        ((size_t)pass * 256 + row) * CIN + (kt + 1) * 64 + seg * 8;
                    CP_ASYNC16(bb + p * 36864 + row * APIT + seg * 16, src);
                }
                CP_COMMIT();
                CP_WAIT(1);
            } else {
                CP_WAIT(0);
            }
            __syncthreads();

            // compute on buf: A-frags (hi+lo) loaded once per k16, reused
            // across Bh (Ah*Bh + Al*Bh) and Bl (Ah*Bl)
            const __nv_bfloat16* Ah = (const __nv_bfloat16*)(smc + buf * 36864);
            const __nv_bfloat16* Al = (const __nv_bfloat16*)(smc + buf * 36864 + 18432);
            const __nv_bfloat16* Bh = (const __nv_bfloat16*)(smc + 73728 + buf * 73728);
            const __nv_bfloat16* Bl = (const __nv_bfloat16*)(smc + 73728 + buf * 73728 + 36864);
            #pragma unroll
            for (int k16 = 0; k16 < 4; k16++) {
                wmma::fragment<wmma::matrix_a, 16, 16, 16, __nv_bfloat16, wmma::row_major> ah[2], al[2];
                #pragma unroll
                for (int i = 0; i < 2; i++) {
                    wmma::load_matrix_sync(ah[i], Ah + (mtb + i) * 16 * APITE + k16 * 16, APITE);
                    wmma::load_matrix_sync(al[i], Al + (mtb + i) * 16 * APITE + k16 * 16, APITE);
                }
                #pragma unroll
                for (int j = 0; j < 4; j++) {
                    wmma::fragment<wmma::matrix_b, 16, 16, 16, __nv_bfloat16, wmma::col_major> b;
                    wmma::load_matrix_sync(b, Bh + (ntb + j) * 16 * APITE + k16 * 16, APITE);
                    wmma::mma_sync(c[0][j], ah[0], b, c[0][j]);
                    wmma::mma_sync(c[1][j], ah[1], b, c[1][j]);
                    wmma::mma_sync(c[0][j], al[0], b, c[0][j]);
                    wmma::mma_sync(c[1][j], al[1], b, c[1][j]);
                    wmma::load_matrix_sync(b, Bl + (ntb + j) * 16 * APITE + k16 * 16, APITE);
                    wmma::mma_sync(c[0][j], ah[0], b, c[0][j]);
                    wmma::mma_sync(c[1][j], ah[1], b, c[1][j]);
                }
            }
            __syncthreads();
        }

        // ---- store C tiles into lg / xw ----
        #pragma unroll
        for (int i = 0; i < 2; i++)
            #pragma unroll
            for (int j = 0; j < 4; j++) {
                int mt = mtb + i, nt = ntb + j;
                int head = nt >> 3, ccb = (nt & 7) * 16;
                float* dst = (ccb < 64 ? lg + head * HSTR + ccb
                                       : xw + head * HSTR + (ccb - 64)) + mt * 16 * PIT;
                wmma::store_matrix_sync(dst, c[i][j], PIT, wmma::mem_row_major);
            }
        // stage dneg + Ahat
        if (tid < NN) dnl[tid] = g_dneg[l * NN + tid];
        if (l > 0)
            for (int i = tid; i < NN * NN; i += NTH) ahm[i] = g_Ahat[l * NN * NN + i];
        __syncthreads();

        // ---- column softmax (head, batch, column m; over n) ----
        if (tid < 2 * 2 * NN) {
            int head = tid / (2 * NN);
            int rr = tid - head * 2 * NN;
            int batch = rr / NN, m = rr - batch * NN;
            float* col = lg + head * HSTR + batch * 64 * PIT + m;
            float mx = -1e30f;
            #pragma unroll 1
            for (int n = 0; n < NN; n++) {
                float v = dnl[n] * col[n * PIT];
                v = (v > 0.f) ? v : 0.01f * v;
                col[n * PIT] = v;
                mx = fmaxf(mx, v);
            }
            float ssum = 0.f;
            #pragma unroll 1
            for (int n = 0; n < NN; n++) {
                float e = __expf(col[n * PIT] - mx);
                col[n * PIT] = e;
                ssum += e;
            }
            float inv = 1.f / ssum;
            #pragma unroll 1
            for (int n = 0; n < NN; n++) col[n * PIT] *= inv;
        }

        // ---- axw = Ahat @ xw (layer 0: 2*xw) ----
        const int g2 = tid >> 8, tile = tid & 255;
        const int m0 = (tile >> 4) * 4, o0 = (tile & 15) * 4;
        if (l == 0) {
            for (int i = tid; i < 2 * 128 * 64; i += NTH) {
                int head = i >> 13, rem = i & 8191;
                int row = rem >> 6, o = rem & 63;
                axw[head * HSTR + row * PIT + o] = 2.f * xw[head * HSTR + row * PIT + o];
            }
        } else {
            for (int gi = 0; gi < 2; gi++) {
                int grp = gi * 2 + g2;
                int head = grp >> 1, batch = grp & 1;
                const float* xb = xw + head * HSTR + batch * 64 * PIT;
                float acc[4][4];
                #pragma unroll
                for (int i = 0; i < 4; i++)
                    #pragma unroll
                    for (int j = 0; j < 4; j++) acc[i][j] = 0.f;
                #pragma unroll 2
                for (int j = 0; j < NN; j++) {
                    float av[4], wv[4];
                    #pragma unroll
                    for (int i = 0; i < 4; i++)
                        av[i] = (m0 + i < NN) ? ahm[(m0 + i) * NN + j] : 0.f;
                    #pragma unroll
                    for (int jj = 0; jj < 4; jj++) wv[jj] = xb[j * PIT + o0 + jj];
                    #pragma unroll
                    for (int i = 0; i < 4; i++)
                        #pragma unroll
                        for (int jj = 0; jj < 4; jj++) acc[i][jj] += av[i] * wv[jj];
                }
                float* ab = axw + head * HSTR + batch * 64 * PIT;
                #pragma unroll
                for (int i = 0; i < 4; i++)
                    if (m0 + i < NN)
                        #pragma unroll
                        for (int jj = 0; jj < 4; jj++)
                            ab[(m0 + i) * PIT + o0 + jj] = acc[i][jj];
            }
        }
        __syncthreads();

        // ---- o = att @ axw ; out RMW ----
        for (int gi = 0; gi < 2; gi++) {
            int grp = gi * 2 + g2;
            int head = grp >> 1, batch = grp & 1;
            const float* ab = lg + head * HSTR + batch * 64 * PIT;
            const float* wb = axw + head * HSTR + batch * 64 * PIT;
            float acc[4][4];
            #pragma unroll
            for (int i = 0; i < 4; i++)
                #pragma unroll
                for (int j = 0; j < 4; j++) acc[i][j] = 0.f;
            #pragma unroll 2
            for (int m = 0; m < NN; m++) {
                float av[4], wv[4];
                #pragma unroll
                for (int i = 0; i < 4; i++) av[i] = ab[(m0 + i) * PIT + m];
                #pragma unroll
                for (int jj = 0; jj < 4; jj++) wv[jj] = wb[m * PIT + o0 + jj];
                #pragma unroll
                for (int i = 0; i < 4; i++)
                    #pragma unroll
                    for (int jj = 0; jj < 4; jj++) acc[i][jj] += av[i] * wv[jj];
            }
            int hg = ph * 2 + head;
            #pragma unroll
            for (int i = 0; i < 4; i++) {
                int n = m0 + i;
                if (n < NN) {
                    float4 add;
                    add.x = fmaxf(acc[i][0], 0.f);
                    add.y = fmaxf(acc[i][1], 0.f);
                    add.z = fmaxf(acc[i][2], 0.f);
                    add.w = fmaxf(acc[i][3], 0.f);
                    float4* op = (float4*)(out + ((size_t)(b2 + batch) * NN + n) * 512 + hg * 64 + o0);
                    if (pass < 4) {
                        *op = add;
                    } else if (pass < 8) {
                        float4 o4 = *op;
                        o4.x += add.x; o4.y += add.y; o4.z += add.z; o4.w += add.w;
                        *op = o4;
                    } else {
                        float4 o4 = *op;
                        o4.x = fmaxf(o4.x + add.x, 0.f);
                        o4.y = fmaxf(o4.y + add.y, 0.f);
                        o4.z = fmaxf(o4.z + add.z, 0.f);
                        o4.w = fmaxf(o4.w + add.w, 0.f);
                        *op = o4;
                    }
                }
            }
        }
        __syncthreads();
    }
}

extern "C" void kernel_launch(void* const* d_in, const int* in_sizes, int n_in,
                              void* d_out, int out_size) {
    const float* x   = (const float*)d_in[0];
    const float* L   = (const float*)d_in[1];
    const float* Wal = (const float*)d_in[2];
    const float* W   = (const float*)d_in[3];
    float* out = (float*)d_out;

    cudaFuncSetAttribute(gat_wmma, cudaFuncAttributeMaxDynamicSharedMemorySize, SMEM_BYTES);
    conv_x<<<8192, 256>>>(x);
    conv_w<<<3072, 256>>>(Wal, W);
    precompute_adj<<<1, 256>>>(L);
    gat_wmma<<<NB / 2, NTH, SMEM_BYTES>>>(out);
}

// round 7
// speedup vs baseline: 5.6916x; 1.2281x over previous
#include <cuda_runtime.h>
#include <cuda_fp16.h>
#include <mma.h>
#include <cstdint>
#include <cstddef>

using namespace nvcuda;

#define NN 62
#define CIN 512
#define NLAY 3
#define NHEAD 8
#define CO 64
#define NB 2048
#define NTH 256
#define PIT 68
#define APITE 72            // A/B smem row pitch in halves (144B) — conflict-free ldmatrix

// ---------------- device global scratch ----------------
__device__ __half g_xh[(size_t)NB * NN * CIN];
__device__ __half g_xl[(size_t)NB * NN * CIN];
__device__ __half g_Bh[NLAY * NHEAD * 128 * CIN];
__device__ float g_Ahat[NLAY * NN * NN];
__device__ float g_dneg[NLAY * NN];

// ---------------- helpers ----------------
__device__ __forceinline__ uint32_t smem_u32(const void* p) {
    uint32_t a;
    asm("{ .reg .u64 t; cvta.to.shared.u64 t, %1; cvt.u32.u64 %0, t; }" : "=r"(a) : "l"(p));
    return a;
}
#define CP_ASYNC16(dst, src) \
    asm volatile("cp.async.cg.shared.global [%0], [%1], 16;" :: "r"(dst), "l"(src) : "memory")
#define CP_COMMIT() asm volatile("cp.async.commit_group;" ::: "memory")
#define CP_WAIT(n)  asm volatile("cp.async.wait_group %0;" :: "n"(n) : "memory")

// ---------------- precompute kernels ----------------
__global__ void conv_x(const float* __restrict__ x) {
    size_t n8 = (size_t)NB * NN * CIN / 8;
    for (size_t i = blockIdx.x * (size_t)blockDim.x + threadIdx.x; i < n8;
         i += (size_t)gridDim.x * blockDim.x) {
        const float4* s = (const float4*)x + i * 2;
        float4 v0 = s[0], v1 = s[1];
        float f[8] = {v0.x, v0.y, v0.z, v0.w, v1.x, v1.y, v1.z, v1.w};
        alignas(16) __half h[8], lo[8];
        #pragma unroll
        for (int j = 0; j < 8; j++) {
            h[j] = __float2half(f[j]);
            lo[j] = __float2half(f[j] - __half2float(h[j]));
        }
        *(uint4*)(g_xh + i * 8) = *(const uint4*)h;
        *(uint4*)(g_xl + i * 8) = *(const uint4*)lo;
    }
}
// g_Bh[(l*8+head)][c(0..127)][k]: c<62 -> Walpha col c, c in [64,128) -> W col c-64, else 0
__global__ void conv_w(const float* __restrict__ Wal, const float* __restrict__ Wo) {
    int total = NLAY * NHEAD * 128 * CIN;
    for (int i = blockIdx.x * blockDim.x + threadIdx.x; i < total; i += gridDim.x * blockDim.x) {
        int k = i & 511;
        int t = i >> 9;
        int c = t & 127;
        int lh = t >> 7;            // l*8 + head
        float v = 0.f;
        if (c < NN) v = Wal[((size_t)lh * CIN + k) * NN + c];
        else if (c >= 64) v = Wo[((size_t)lh * CIN + k) * CO + (c - 64)];
        g_Bh[i] = __float2half(v);
    }
}
__global__ void precompute_adj(const float* __restrict__ L) {
    __shared__ float D1s[NN];
    int tid = threadIdx.x;
    if (tid < NN) {
        float s = 0.f;
        for (int m = 0; m < NN; m++) s += L[tid * NN + m];
        D1s[tid] = s;
    }
    __syncthreads();
    if (tid < NN) {
        g_dneg[tid] = 1.0f;
        float d1 = D1s[tid];
        g_dneg[NN + tid] = (d1 == 0.f) ? 0.f : (1.f / d1);
        float d2 = 0.f;
        for (int k = 0; k < NN; k++) d2 += L[tid * NN + k] * D1s[k];
        g_dneg[2 * NN + tid] = (d2 == 0.f) ? 0.f : (1.f / d2);
    }
    for (int idx = tid; idx < NN * NN; idx += blockDim.x) {
        int n = idx / NN, m = idx - n * NN;
        float eye = (n == m) ? 1.f : 0.f;
        g_Ahat[idx] = 2.f * eye;
        g_Ahat[NN * NN + idx] = L[idx] + eye;
        float a2 = 0.f;
        for (int k = 0; k < NN; k++) a2 += L[n * NN + k] * L[k * NN + m];
        g_Ahat[2 * NN * NN + idx] = a2 + eye;
    }
}

// ---------------- main kernel ----------------
// smem (bytes), MMA phase:
//   A(buf,plane) = buf*36864 + plane*18432   [0, 73728)    (128 rows x 144B)
//   B(buf)       = 73728 + buf*18432         [73728, 110592)
// EPI overlay:  lg@0 (128x68 f32)  xw@34816  axw@69632 (64x68)  ahm@87040 (62x62)  dnl@102416
#define SMEM_BYTES 110592

__global__ __launch_bounds__(NTH, 2) void gat_wmma(float* __restrict__ out) {
    extern __shared__ char smc[];
    const uint32_t smb = smem_u32(smc);
    const int tid = threadIdx.x;
    const int warp = tid >> 5;
    const int b2 = blockIdx.x * 2;

    float* lg  = (float*)(smc + 0);
    float* xw  = (float*)(smc + 34816);
    float* axw = (float*)(smc + 69632);
    float* ahm = (float*)(smc + 87040);
    float* dnl = (float*)(smc + 102416);

    // warp grid 4 rows x 2 cols; warp owns 2 M-tiles x 4 N-tiles (16x16 each)
    const int wr = warp >> 1, wc = warp & 1;
    const int mtb = wr * 2;
    const int ntb = wc * 4;

    for (int pass = 0; pass < 24; pass++) {
        const int l = pass >> 3, head = pass & 7;

        // ---- zero A padding rows (62,63,126,127) x 2 planes x 2 bufs ----
        if (tid < 128) {
            int seg = tid & 7, r = (tid >> 3) & 3, plane = (tid >> 5) & 1, buf = (tid >> 6) & 1;
            int row = (r >> 1) * 64 + 62 + (r & 1);
            *(uint4*)(smc + buf * 36864 + plane * 18432 + row * 144 + seg * 16) =
                make_uint4(0, 0, 0, 0);
        }

        wmma::fragment<wmma::accumulator, 16, 16, 16, float> c[2][4];
        #pragma unroll
        for (int i = 0; i < 2; i++)
            #pragma unroll
            for (int j = 0; j < 4; j++) wmma::fill_fragment(c[i][j], 0.f);

        // ---- prefetch kt=0 into buf 0 ----
        {
            const uint32_t ab = smb;
            for (int u = tid; u < 2048; u += NTH) {
                int p = u >> 10, idx = u & 1023;
                int row = idx >> 3, seg = idx & 7;
                int nn = row & 63;
                if (nn < NN) {
                    const __half* src = (p ? g_xl : g_xh) +
                        ((size_t)(b2 + (row >> 6)) * NN + nn) * CIN + seg * 8;
                    CP_ASYNC16(ab + p * 18432 + row * 144 + seg * 16, src);
                }
            }
            const uint32_t bb = smb + 73728;
            for (int u = tid; u < 1024; u += NTH) {
                int row = u >> 3, seg = u & 7;
                const __half* src = g_Bh + ((size_t)pass * 128 + row) * CIN + seg * 8;
                CP_ASYNC16(bb + row * 144 + seg * 16, src);
            }
            CP_COMMIT();
        }

        // ---- K loop: 8 chunks of 64, double buffered ----
        for (int kt = 0; kt < 8; kt++) {
            const int buf = kt & 1;
            if (kt < 7) {
                const int nbuf = buf ^ 1;
                const uint32_t ab = smb + nbuf * 36864;
                for (int u = tid; u < 2048; u += NTH) {
                    int p = u >> 10, idx = u & 1023;
                    int row = idx >> 3, seg = idx & 7;
                    int nn = row & 63;
                    if (nn < NN) {
                        const __half* src = (p ? g_xl : g_xh) +
                            ((size_t)(b2 + (row >> 6)) * NN + nn) * CIN + (kt + 1) * 64 + seg * 8;
                        CP_ASYNC16(ab + p * 18432 + row * 144 + seg * 16, src);
                    }
                }
                const uint32_t bb = smb + 73728 + nbuf * 18432;
                for (int u = tid; u < 1024; u += NTH) {
                    int row = u >> 3, seg = u & 7;
                    const __half* src = g_Bh + ((size_t)pass * 128 + row) * CIN +
                                        (kt + 1) * 64 + seg * 8;
                    CP_ASYNC16(bb + row * 144 + seg * 16, src);
                }
                CP_COMMIT();
                CP_WAIT(1);
            } else {
                CP_WAIT(0);
            }
            __syncthreads();

            const __half* Ah = (const __half*)(smc + buf * 36864);
            const __half* Al = (const __half*)(smc + buf * 36864 + 18432);
            const __half* Bs = (const __half*)(smc + 73728 + buf * 18432);
            #pragma unroll
            for (int k16 = 0; k16 < 4; k16++) {
                wmma::fragment<wmma::matrix_a, 16, 16, 16, __half, wmma::row_major> ah[2], al[2];
                #pragma unroll
                for (int i = 0; i < 2; i++) {
                    wmma::load_matrix_sync(ah[i], Ah + (mtb + i) * 16 * APITE + k16 * 16, APITE);
                    wmma::load_matrix_sync(al[i], Al + (mtb + i) * 16 * APITE + k16 * 16, APITE);
                }
                #pragma unroll
                for (int j = 0; j < 4; j++) {
                    wmma::fragment<wmma::matrix_b, 16, 16, 16, __half, wmma::col_major> b;
                    wmma::load_matrix_sync(b, Bs + (ntb + j) * 16 * APITE + k16 * 16, APITE);
                    wmma::mma_sync(c[0][j], ah[0], b, c[0][j]);
                    wmma::mma_sync(c[1][j], ah[1], b, c[1][j]);
                    wmma::mma_sync(c[0][j], al[0], b, c[0][j]);
                    wmma::mma_sync(c[1][j], al[1], b, c[1][j]);
                }
            }
            __syncthreads();
        }

        // ---- store C tiles into lg / xw ; stage ahm/dnl ----
        #pragma unroll
        for (int i = 0; i < 2; i++)
            #pragma unroll
            for (int j = 0; j < 4; j++) {
                int mt = mtb + i, nt = ntb + j;
                float* dst = (nt < 4 ? lg + nt * 16 : xw + (nt - 4) * 16) + mt * 16 * PIT;
                wmma::store_matrix_sync(dst, c[i][j], PIT, wmma::mem_row_major);
            }
        if (tid < NN) dnl[tid] = g_dneg[l * NN + tid];
        if (l > 0)
            for (int i = tid; i < NN * NN; i += NTH) ahm[i] = g_Ahat[l * NN * NN + i];
        __syncthreads();

        // ---- column softmax: 256 threads = 128 (batch,col) x 2 halves ----
        {
            int cc = tid >> 1, half = tid & 1;
            int batch = cc >> 6, m = cc & 63;   // m 62,63 = harmless scratch cols
            float* base = lg + batch * 64 * PIT + m;
            int nlo = half * 31;
            float mx = -1e30f;
            #pragma unroll 1
            for (int n = nlo; n < nlo + 31; n++) {
                float v = dnl[n] * base[n * PIT];
                v = (v > 0.f) ? v : 0.01f * v;
                base[n * PIT] = v;
                mx = fmaxf(mx, v);
            }
            mx = fmaxf(mx, __shfl_xor_sync(0xffffffffu, mx, 1));
            float ssum = 0.f;
            #pragma unroll 1
            for (int n = nlo; n < nlo + 31; n++) {
                float e = __expf(base[n * PIT] - mx);
                base[n * PIT] = e;
                ssum += e;
            }
            ssum += __shfl_xor_sync(0xffffffffu, ssum, 1);
            float inv = 1.f / ssum;
            #pragma unroll 1
            for (int n = nlo; n < nlo + 31; n++) base[n * PIT] *= inv;
        }
        __syncthreads();

        // ---- per-batch: axw = Ahat @ xw (l>0), then o = att @ axw, out RMW ----
        const int rt = tid >> 4, ct = tid & 15;
        const int r0 = rt * 4, o0 = ct * 4;
        for (int bt = 0; bt < 2; bt++) {
            const float* xb = xw + bt * 64 * PIT;
            if (l > 0) {
                float acc[4][4];
                #pragma unroll
                for (int i = 0; i < 4; i++)
                    #pragma unroll
                    for (int j = 0; j < 4; j++) acc[i][j] = 0.f;
                #pragma unroll 2
                for (int j = 0; j < NN; j++) {
                    float av[4];
                    #pragma unroll
                    for (int i = 0; i < 4; i++)
                        av[i] = (r0 + i < NN) ? ahm[(r0 + i) * NN + j] : 0.f;
                    float4 wv = *(const float4*)(xb + j * PIT + o0);
                    #pragma unroll
                    for (int i = 0; i < 4; i++) {
                        acc[i][0] += av[i] * wv.x;
                        acc[i][1] += av[i] * wv.y;
                        acc[i][2] += av[i] * wv.z;
                        acc[i][3] += av[i] * wv.w;
                    }
                }
                #pragma unroll
                for (int i = 0; i < 4; i++)
                    if (r0 + i < NN)
                        *(float4*)(axw + (r0 + i) * PIT + o0) =
                            make_float4(acc[i][0], acc[i][1], acc[i][2], acc[i][3]);
                __syncthreads();
            }
            const float* wb = (l == 0) ? xb : axw;
            const float scl = (l == 0) ? 2.f : 1.f;
            const float* ab = lg + bt * 64 * PIT;
            float acc[4][4];
            #pragma unroll
            for (int i = 0; i < 4; i++)
                #pragma unroll
                for (int j = 0; j < 4; j++) acc[i][j] = 0.f;
            #pragma unroll 2
            for (int m = 0; m < NN; m++) {
                float av[4];
                #pragma unroll
                for (int i = 0; i < 4; i++) av[i] = ab[(r0 + i) * PIT + m];
                float4 wv = *(const float4*)(wb + m * PIT + o0);
                #pragma unroll
                for (int i = 0; i < 4; i++) {
                    acc[i][0] += av[i] * wv.x;
                    acc[i][1] += av[i] * wv.y;
                    acc[i][2] += av[i] * wv.z;
                    acc[i][3] += av[i] * wv.w;
                }
            }
            #pragma unroll
            for (int i = 0; i < 4; i++) {
                int n = r0 + i;
                if (n < NN) {
                    float4 add;
                    add.x = fmaxf(scl * acc[i][0], 0.f);
                    add.y = fmaxf(scl * acc[i][1], 0.f);
                    add.z = fmaxf(scl * acc[i][2], 0.f);
                    add.w = fmaxf(scl * acc[i][3], 0.f);
                    float4* op = (float4*)(out + ((size_t)(b2 + bt) * NN + n) * 512 +
                                           head * 64 + o0);
                    if (l == 0) {
                        *op = add;
                    } else if (l == 1) {
                        float4 o4 = *op;
                        o4.x += add.x; o4.y += add.y; o4.z += add.z; o4.w += add.w;
                        *op = o4;
                    } else {
                        float4 o4 = *op;
                        o4.x = fmaxf(o4.x + add.x, 0.f);
                        o4.y = fmaxf(o4.y + add.y, 0.f);
                        o4.z = fmaxf(o4.z + add.z, 0.f);
                        o4.w = fmaxf(o4.w + add.w, 0.f);
                        *op = o4;
                    }
                }
            }
            if (l > 0 && bt == 0) __syncthreads();  // protect axw before overwrite
        }
        __syncthreads();
    }
}

extern "C" void kernel_launch(void* const* d_in, const int* in_sizes, int n_in,
                              void* d_out, int out_size) {
    const float* x   = (const float*)d_in[0];
    const float* L   = (const float*)d_in[1];
    const float* Wal = (const float*)d_in[2];
    const float* W   = (const float*)d_in[3];
    float* out = (float*)d_out;

    cudaFuncSetAttribute(gat_wmma, cudaFuncAttributeMaxDynamicSharedMemorySize, SMEM_BYTES);
    conv_x<<<8192, 256>>>(x);
    conv_w<<<3072, 256>>>(Wal, W);
    precompute_adj<<<1, 256>>>(L);
    gat_wmma<<<NB / 2, NTH, SMEM_BYTES>>>(out);
}

// round 11
// speedup vs baseline: 6.7088x; 1.1787x over previous
#include <cuda_runtime.h>
#include <cuda_fp16.h>
#include <mma.h>
#include <cstdint>
#include <cstddef>

using namespace nvcuda;

#define NN 62
#define CIN 512
#define NLAY 3
#define NHEAD 8
#define CO 64
#define NB 2048
#define NTH 512
#define PIT 68
#define HSTRF (128 * PIT)      // floats per head block in lg/xw

// ---------------- device global scratch ----------------
__device__ __half g_xh[(size_t)NB * NN * CIN];
__device__ __half g_xl[(size_t)NB * NN * CIN];
__device__ __half g_Bh[NLAY * NHEAD * 128 * CIN];
__device__ __half g_AhH[NLAY * 64 * 72];
__device__ __half g_AhL[NLAY * 64 * 72];
__device__ float g_Ahat[NLAY * NN * NN];
__device__ float g_dneg[NLAY * NN];

// ---------------- helpers ----------------
__device__ __forceinline__ uint32_t smem_u32(const void* p) {
    uint32_t a;
    asm("{ .reg .u64 t; cvta.to.shared.u64 t, %1; cvt.u32.u64 %0, t; }" : "=r"(a) : "l"(p));
    return a;
}
#define CP_ASYNC16(dst, src) \
    asm volatile("cp.async.cg.shared.global [%0], [%1], 16;" :: "r"(dst), "l"(src) : "memory")
#define CP_COMMIT() asm volatile("cp.async.commit_group;" ::: "memory")
#define CP_WAIT(n)  asm volatile("cp.async.wait_group %0;" :: "n"(n) : "memory")

// ---------------- precompute kernels ----------------
__global__ void conv_x(const float* __restrict__ x) {
    size_t n8 = (size_t)NB * NN * CIN / 8;
    for (size_t i = blockIdx.x * (size_t)blockDim.x + threadIdx.x; i < n8;
         i += (size_t)gridDim.x * blockDim.x) {
        const float4* s = (const float4*)x + i * 2;
        float4 v0 = s[0], v1 = s[1];
        float f[8] = {v0.x, v0.y, v0.z, v0.w, v1.x, v1.y, v1.z, v1.w};
        alignas(16) __half h[8], lo[8];
        #pragma unroll
        for (int j = 0; j < 8; j++) {
            h[j] = __float2half(f[j]);
            lo[j] = __float2half(f[j] - __half2float(h[j]));
        }
        *(uint4*)(g_xh + i * 8) = *(const uint4*)h;
        *(uint4*)(g_xl + i * 8) = *(const uint4*)lo;
    }
}
// g_Bh[(l*8+head)][c(0..127)][k]: c<62 -> Walpha col c, c in [64,128) -> W col c-64, else 0
__global__ void conv_w(const float* __restrict__ Wal, const float* __restrict__ Wo) {
    int total = NLAY * NHEAD * 128 * CIN;
    for (int i = blockIdx.x * blockDim.x + threadIdx.x; i < total; i += gridDim.x * blockDim.x) {
        int k = i & 511;
        int t = i >> 9;
        int c = t & 127;
        int lh = t >> 7;
        float v = 0.f;
        if (c < NN) v = Wal[((size_t)lh * CIN + k) * NN + c];
        else if (c >= 64) v = Wo[((size_t)lh * CIN + k) * CO + (c - 64)];
        g_Bh[i] = __float2half(v);
    }
}
__global__ void precompute_adj(const float* __restrict__ L) {
    __shared__ float D1s[NN];
    int tid = threadIdx.x;
    if (tid < NN) {
        float s = 0.f;
        for (int m = 0; m < NN; m++) s += L[tid * NN + m];
        D1s[tid] = s;
    }
    __syncthreads();
    if (tid < NN) {
        g_dneg[tid] = 1.0f;
        float d1 = D1s[tid];
        g_dneg[NN + tid] = (d1 == 0.f) ? 0.f : (1.f / d1);
        float d2 = 0.f;
        for (int k = 0; k < NN; k++) d2 += L[tid * NN + k] * D1s[k];
        g_dneg[2 * NN + tid] = (d2 == 0.f) ? 0.f : (1.f / d2);
    }
    for (int idx = tid; idx < NN * NN; idx += blockDim.x) {
        int n = idx / NN, m = idx - n * NN;
        float eye = (n == m) ? 1.f : 0.f;
        g_Ahat[idx] = 2.f * eye;
        g_Ahat[NN * NN + idx] = L[idx] + eye;
        float a2 = 0.f;
        for (int k = 0; k < NN; k++) a2 += L[n * NN + k] * L[k * NN + m];
        g_Ahat[2 * NN * NN + idx] = a2 + eye;
    }
    __syncthreads();
    // fp16 hi/lo split of Ahat, padded [64][72], pad = 0
    for (int idx = tid; idx < NLAY * 64 * 72; idx += blockDim.x) {
        int l = idx / (64 * 72), rem = idx - l * 64 * 72;
        int r = rem / 72, c = rem - r * 72;
        float v = (r < NN && c < NN) ? g_Ahat[l * NN * NN + r * NN + c] : 0.f;
        __half h = __float2half(v);
        g_AhH[idx] = h;
        g_AhL[idx] = __float2half(v - __half2float(h));
    }
}

// ---------------- main kernel ----------------
// smem (bytes), MMA phase:
//   A(buf,plane) = buf*36864 + plane*18432   [0, 73728)   (128 rows x 144B)
//   B(buf)       = 73728 + buf*36864          [73728, 147456)  (256 rows x 144B)
// EPI overlay: lg@0 [2][128][68]f32 (69632)  xw@69632 (69632)
//   ahH@139264 ahL@148480 attH@157696 attL@166912 bH@176128 bL@185344  dnl@194560
#define SMEM_BYTES 194816

__global__ __launch_bounds__(NTH, 1) void gat_wmma(float* __restrict__ out) {
    extern __shared__ char smc[];
    const uint32_t smb = smem_u32(smc);
    const int tid = threadIdx.x;
    const int warp = tid >> 5;
    const int b2 = blockIdx.x * 2;

    float* lg  = (float*)(smc + 0);
    float* xw  = (float*)(smc + 69632);
    __half* ahH  = (__half*)(smc + 139264);
    __half* ahL  = (__half*)(smc + 148480);
    __half* attH = (__half*)(smc + 157696);
    __half* attL = (__half*)(smc + 166912);
    __half* bH   = (__half*)(smc + 176128);
    __half* bL   = (__half*)(smc + 185344);
    float* dnl = (float*)(smc + 194560);

    // main-GEMM warp grid: 8 M-tiles x 16 N-tiles; warp owns 2M x 4N
    const int mtb = (warp >> 2) * 2;
    const int ntb = (warp & 3) * 4;

    for (int pass = 0; pass < 12; pass++) {
        const int l = pass >> 2, ph = pass & 3;

        // ---- zero A pad rows (62,63,126,127) x 2 planes x 2 bufs ----
        if (tid < 128) {
            int seg = tid & 7, r = (tid >> 3) & 3, plane = (tid >> 5) & 1, buf = (tid >> 6) & 1;
            int row = (r >> 1) * 64 + 62 + (r & 1);
            *(uint4*)(smc + buf * 36864 + plane * 18432 + row * 144 + seg * 16) =
                make_uint4(0, 0, 0, 0);
        }

        wmma::fragment<wmma::accumulator, 16, 16, 16, float> c[2][4];
        #pragma unroll
        for (int i = 0; i < 2; i++)
            #pragma unroll
            for (int j = 0; j < 4; j++) wmma::fill_fragment(c[i][j], 0.f);

        // ---- prefetch kt=0 into buf 0 ----
        {
            for (int u = tid; u < 2048; u += NTH) {
                int p = u >> 10, idx = u & 1023;
                int row = idx >> 3, seg = idx & 7;
                int nn = row & 63;
                if (nn < NN) {
                    const __half* src = (p ? g_xl : g_xh) +
                        ((size_t)(b2 + (row >> 6)) * NN + nn) * CIN + seg * 8;
                    CP_ASYNC16(smb + p * 18432 + row * 144 + seg * 16, src);
                }
            }
            for (int u = tid; u < 2048; u += NTH) {
                int row = u >> 3, seg = u & 7;
                const __half* src = g_Bh + ((size_t)(l * 1024 + ph * 256 + row)) * CIN + seg * 8;
                CP_ASYNC16(smb + 73728 + row * 144 + seg * 16, src);
            }
            CP_COMMIT();
        }

        // ---- K loop: 8 chunks of 64, double buffered ----
        for (int kt = 0; kt < 8; kt++) {
            const int buf = kt & 1;
            if (kt < 7) {
                const int nbuf = buf ^ 1;
                for (int u = tid; u < 2048; u += NTH) {
                    int p = u >> 10, idx = u & 1023;
                    int row = idx >> 3, seg = idx & 7;
                    int nn = row & 63;
                    if (nn < NN) {
                        const __half* src = (p ? g_xl : g_xh) +
                            ((size_t)(b2 + (row >> 6)) * NN + nn) * CIN + (kt + 1) * 64 + seg * 8;
                        CP_ASYNC16(smb + nbuf * 36864 + p * 18432 + row * 144 + seg * 16, src);
                    }
                }
                for (int u = tid; u < 2048; u += NTH) {
                    int row = u >> 3, seg = u & 7;
                    const __half* src = g_Bh + ((size_t)(l * 1024 + ph * 256 + row)) * CIN +
                                        (kt + 1) * 64 + seg * 8;
                    CP_ASYNC16(smb + 73728 + nbuf * 36864 + row * 144 + seg * 16, src);
                }
                CP_COMMIT();
                CP_WAIT(1);
            } else {
                CP_WAIT(0);
            }
            __syncthreads();

            const __half* Ah = (const __half*)(smc + buf * 36864);
            const __half* Al = (const __half*)(smc + buf * 36864 + 18432);
            const __half* Bs = (const __half*)(smc + 73728 + buf * 36864);
            #pragma unroll
            for (int k16 = 0; k16 < 4; k16++) {
                wmma::fragment<wmma::matrix_a, 16, 16, 16, __half, wmma::row_major> ah[2], al[2];
                #pragma unroll
                for (int i = 0; i < 2; i++) {
                    wmma::load_matrix_sync(ah[i], Ah + (mtb + i) * 16 * 72 + k16 * 16, 72);
                    wmma::load_matrix_sync(al[i], Al + (mtb + i) * 16 * 72 + k16 * 16, 72);
                }
                #pragma unroll
                for (int j = 0; j < 4; j++) {
                    wmma::fragment<wmma::matrix_b, 16, 16, 16, __half, wmma::col_major> b;
                    wmma::load_matrix_sync(b, Bs + (ntb + j) * 16 * 72 + k16 * 16, 72);
                    wmma::mma_sync(c[0][j], ah[0], b, c[0][j]);
                    wmma::mma_sync(c[1][j], ah[1], b, c[1][j]);
                    wmma::mma_sync(c[0][j], al[0], b, c[0][j]);
                    wmma::mma_sync(c[1][j], al[1], b, c[1][j]);
                }
            }
            __syncthreads();
        }

        // ---- store C into lg/xw; stage ahm hi/lo + dnl ----
        #pragma unroll
        for (int i = 0; i < 2; i++)
            #pragma unroll
            for (int j = 0; j < 4; j++) {
                int mt = mtb + i, nt = ntb + j;
                int head = nt >> 3, cb = (nt & 7) * 16;
                float* dst = (cb < 64 ? lg + head * HSTRF + cb
                                      : xw + head * HSTRF + (cb - 64)) + mt * 16 * PIT;
                wmma::store_matrix_sync(dst, c[i][j], PIT, wmma::mem_row_major);
            }
        if (tid < NN) dnl[tid] = g_dneg[l * NN + tid];
        if (l > 0) {
            for (int i = tid; i < 64 * 72 / 8; i += NTH) {
                *(uint4*)((char*)ahH + i * 16) = *(const uint4*)((const char*)(g_AhH + l * 64 * 72) + i * 16);
                *(uint4*)((char*)ahL + i * 16) = *(const uint4*)((const char*)(g_AhL + l * 64 * 72) + i * 16);
            }
        }
        __syncthreads();

        // ---- softmax: 512 thr = 4 units x 64 cols x 2 halves ----
        // NOTE: no (m < NN) guard — shuffles must be warp-uniform. Columns 62/63
        // are harmless scratch: they multiply axw rows 62/63 which are exactly 0.
        {
            int unit = tid >> 7, rem = tid & 127;
            int m = rem >> 1, half = rem & 1;
            int head = unit >> 1, bt = unit & 1;
            float* col = lg + head * HSTRF + bt * 64 * PIT + m;
            int nlo = half * 31;
            float mx = -1e30f;
            #pragma unroll 1
            for (int n = nlo; n < nlo + 31; n++) {
                float v = dnl[n] * col[n * PIT];
                v = (v > 0.f) ? v : 0.01f * v;
                col[n * PIT] = v;
                mx = fmaxf(mx, v);
            }
            mx = fmaxf(mx, __shfl_xor_sync(0xffffffffu, mx, 1));
            float ssum = 0.f;
            #pragma unroll 1
            for (int n = nlo; n < nlo + 31; n++) {
                float e = __expf(col[n * PIT] - mx);
                col[n * PIT] = e;
                ssum += e;
            }
            ssum += __shfl_xor_sync(0xffffffffu, ssum, 1);
            float inv = 1.f / ssum;
            #pragma unroll 1
            for (int n = nlo; n < nlo + 31; n++) col[n * PIT] *= inv;
        }
        __syncthreads();

        // ---- per (head,batch) unit: WMMA small GEMMs ----
        const int smt = warp >> 2, snt = warp & 3;   // 16 warps -> 4x4 tile grid (64x64)
        for (int u = 0; u < 4; u++) {
            const int head = u >> 1, bt = u & 1;
            float* lgu = lg + head * HSTRF + bt * 64 * PIT;
            float* xwu = xw + head * HSTRF + bt * 64 * PIT;
            const float scl = (l == 0) ? 2.f : 1.f;

            // convert xw -> bHL (x2 for l=0), att -> attHL
            for (int i = tid; i < 4096; i += NTH) {
                int r = i >> 6, cc = i & 63;
                float v = scl * xwu[r * PIT + cc];
                __half h = __float2half(v);
                bH[r * 72 + cc] = h;
                bL[r * 72 + cc] = __float2half(v - __half2float(h));
                float a = lgu[r * PIT + cc];
                __half ha = __float2half(a);
                attH[r * 72 + cc] = ha;
                attL[r * 72 + cc] = __float2half(a - __half2float(ha));
            }
            __syncthreads();

            if (l > 0) {
                // axw = Ahat @ xw  (3-term) -> store fp32 into xwu
                wmma::fragment<wmma::accumulator, 16, 16, 16, float> f;
                wmma::fill_fragment(f, 0.f);
                #pragma unroll
                for (int k16 = 0; k16 < 4; k16++) {
                    wmma::fragment<wmma::matrix_a, 16, 16, 16, __half, wmma::row_major> aH, aL;
                    wmma::fragment<wmma::matrix_b, 16, 16, 16, __half, wmma::row_major> bHf, bLf;
                    wmma::load_matrix_sync(aH, ahH + smt * 16 * 72 + k16 * 16, 72);
                    wmma::load_matrix_sync(aL, ahL + smt * 16 * 72 + k16 * 16, 72);
                    wmma::load_matrix_sync(bHf, bH + k16 * 16 * 72 + snt * 16, 72);
                    wmma::load_matrix_sync(bLf, bL + k16 * 16 * 72 + snt * 16, 72);
                    wmma::mma_sync(f, aH, bHf, f);
                    wmma::mma_sync(f, aH, bLf, f);
                    wmma::mma_sync(f, aL, bHf, f);
                }
                wmma::store_matrix_sync(xwu + smt * 16 * PIT + snt * 16, f, PIT,
                                        wmma::mem_row_major);
                __syncthreads();
                // convert axw -> bHL (overwrite)
                for (int i = tid; i < 4096; i += NTH) {
                    int r = i >> 6, cc = i & 63;
                    float v = xwu[r * PIT + cc];
                    __half h = __float2half(v);
                    bH[r * 72 + cc] = h;
                    bL[r * 72 + cc] = __float2half(v - __half2float(h));
                }
                __syncthreads();
            }

            // o = att @ b  (3-term) -> store fp32 into lgu
            {
                wmma::fragment<wmma::accumulator, 16, 16, 16, float> f;
                wmma::fill_fragment(f, 0.f);
                #pragma unroll
                for (int k16 = 0; k16 < 4; k16++) {
                    wmma::fragment<wmma::matrix_a, 16, 16, 16, __half, wmma::row_major> aH, aL;
                    wmma::fragment<wmma::matrix_b, 16, 16, 16, __half, wmma::row_major> bHf, bLf;
                    wmma::load_matrix_sync(aH, attH + smt * 16 * 72 + k16 * 16, 72);
                    wmma::load_matrix_sync(aL, attL + smt * 16 * 72 + k16 * 16, 72);
                    wmma::load_matrix_sync(bHf, bH + k16 * 16 * 72 + snt * 16, 72);
                    wmma::load_matrix_sync(bLf, bL + k16 * 16 * 72 + snt * 16, 72);
                    wmma::mma_sync(f, aH, bHf, f);
                    wmma::mma_sync(f, aH, bLf, f);
                    wmma::mma_sync(f, aL, bHf, f);
                }
                wmma::store_matrix_sync(lgu + smt * 16 * PIT + snt * 16, f, PIT,
                                        wmma::mem_row_major);
            }
            __syncthreads();

            // RMW out from lgu
            int hg = (ph * 2 + head);
            for (int i = tid; i < NN * 16; i += NTH) {
                int n = i >> 4, o4 = (i & 15) * 4;
                float4 v = *(const float4*)(lgu + n * PIT + o4);
                float4 add;
                add.x = fmaxf(v.x, 0.f); add.y = fmaxf(v.y, 0.f);
                add.z = fmaxf(v.z, 0.f); add.w = fmaxf(v.w, 0.f);
                float4* op = (float4*)(out + ((size_t)(b2 + bt) * NN + n) * 512 + hg * 64 + o4);
                if (l == 0) {
                    *op = add;
                } else if (l == 1) {
                    float4 o4v = *op;
                    o4v.x += add.x; o4v.y += add.y; o4v.z += add.z; o4v.w += add.w;
                    *op = o4v;
                } else {
                    float4 o4v = *op;
                    o4v.x = fmaxf(o4v.x + add.x, 0.f);
                    o4v.y = fmaxf(o4v.y + add.y, 0.f);
                    o4v.z = fmaxf(o4v.z + add.z, 0.f);
                    o4v.w = fmaxf(o4v.w + add.w, 0.f);
                    *op = o4v;
                }
            }
            __syncthreads();
        }
    }
}

extern "C" void kernel_launch(void* const* d_in, const int* in_sizes, int n_in,
                              void* d_out, int out_size) {
    const float* x   = (const float*)d_in[0];
    const float* L   = (const float*)d_in[1];
    const float* Wal = (const float*)d_in[2];
    const float* W   = (const float*)d_in[3];
    float* out = (float*)d_out;

    cudaFuncSetAttribute(gat_wmma, cudaFuncAttributeMaxDynamicSharedMemorySize, SMEM_BYTES);
    conv_x<<<8192, 256>>>(x);
    conv_w<<<3072, 256>>>(Wal, W);
    precompute_adj<<<1, 256>>>(L);
    gat_wmma<<<NB / 2, NTH, SMEM_BYTES>>>(out);
}

// round 16
// speedup vs baseline: 6.9617x; 1.0377x over previous
#include <cuda_runtime.h>
#include <cuda_fp16.h>
#include <mma.h>
#include <cstdint>
#include <cstddef>

using namespace nvcuda;

#define NN 62
#define CIN 512
#define NLAY 3
#define NHEAD 8
#define CO 64
#define NB 2048
#define NTH 256

// ---------------- device global scratch ----------------
__device__ __half g_xh[(size_t)NB * NN * CIN];
__device__ __half g_xl[(size_t)NB * NN * CIN];
__device__ __half g_Bh[NLAY * NHEAD * 128 * CIN];
__device__ __align__(32) __half g_AhH[NLAY * 64 * 72];
__device__ __align__(32) __half g_AhL[NLAY * 64 * 72];
__device__ float g_Ahat[NLAY * NN * NN];
__device__ float g_dneg[NLAY * NN];

// ---------------- helpers ----------------
__device__ __forceinline__ uint32_t smem_u32(const void* p) {
    uint32_t a;
    asm("{ .reg .u64 t; cvta.to.shared.u64 t, %1; cvt.u32.u64 %0, t; }" : "=r"(a) : "l"(p));
    return a;
}
#define CP_ASYNC16(dst, src) \
    asm volatile("cp.async.cg.shared.global [%0], [%1], 16;" :: "r"(dst), "l"(src) : "memory")
#define CP_COMMIT() asm volatile("cp.async.commit_group;" ::: "memory")
#define CP_WAIT(n)  asm volatile("cp.async.wait_group %0;" :: "n"(n) : "memory")

// ---------------- precompute kernels ----------------
__global__ void conv_x(const float* __restrict__ x) {
    size_t n8 = (size_t)NB * NN * CIN / 8;
    for (size_t i = blockIdx.x * (size_t)blockDim.x + threadIdx.x; i < n8;
         i += (size_t)gridDim.x * blockDim.x) {
        const float4* s = (const float4*)x + i * 2;
        float4 v0 = s[0], v1 = s[1];
        float f[8] = {v0.x, v0.y, v0.z, v0.w, v1.x, v1.y, v1.z, v1.w};
        alignas(16) __half h[8], lo[8];
        #pragma unroll
        for (int j = 0; j < 8; j++) {
            h[j] = __float2half(f[j]);
            lo[j] = __float2half(f[j] - __half2float(h[j]));
        }
        *(uint4*)(g_xh + i * 8) = *(const uint4*)h;
        *(uint4*)(g_xl + i * 8) = *(const uint4*)lo;
    }
}
// g_Bh[(l*8+head)][c(0..127)][k]: c<62 -> Walpha col c, c in [64,128) -> W col c-64, else 0
__global__ void conv_w(const float* __restrict__ Wal, const float* __restrict__ Wo) {
    int total = NLAY * NHEAD * 128 * CIN;
    for (int i = blockIdx.x * blockDim.x + threadIdx.x; i < total; i += gridDim.x * blockDim.x) {
        int k = i & 511;
        int t = i >> 9;
        int c = t & 127;
        int lh = t >> 7;
        float v = 0.f;
        if (c < NN) v = Wal[((size_t)lh * CIN + k) * NN + c];
        else if (c >= 64) v = Wo[((size_t)lh * CIN + k) * CO + (c - 64)];
        g_Bh[i] = __float2half(v);
    }
}
__global__ void precompute_adj(const float* __restrict__ L) {
    __shared__ float D1s[NN];
    int tid = threadIdx.x;
    if (tid < NN) {
        float s = 0.f;
        for (int m = 0; m < NN; m++) s += L[tid * NN + m];
        D1s[tid] = s;
    }
    __syncthreads();
    if (tid < NN) {
        g_dneg[tid] = 1.0f;
        float d1 = D1s[tid];
        g_dneg[NN + tid] = (d1 == 0.f) ? 0.f : (1.f / d1);
        float d2 = 0.f;
        for (int k = 0; k < NN; k++) d2 += L[tid * NN + k] * D1s[k];
        g_dneg[2 * NN + tid] = (d2 == 0.f) ? 0.f : (1.f / d2);
    }
    for (int idx = tid; idx < NN * NN; idx += blockDim.x) {
        int n = idx / NN, m = idx - n * NN;
        float eye = (n == m) ? 1.f : 0.f;
        g_Ahat[idx] = 2.f * eye;
        g_Ahat[NN * NN + idx] = L[idx] + eye;
        float a2 = 0.f;
        for (int k = 0; k < NN; k++) a2 += L[n * NN + k] * L[k * NN + m];
        g_Ahat[2 * NN * NN + idx] = a2 + eye;
    }
    __syncthreads();
    // fp16 hi/lo split of Ahat, padded [64][72], pad = 0
    for (int idx = tid; idx < NLAY * 64 * 72; idx += blockDim.x) {
        int l = idx / (64 * 72), rem = idx - l * 64 * 72;
        int r = rem / 72, c = rem - r * 72;
        float v = (r < NN && c < NN) ? g_Ahat[l * NN * NN + r * NN + c] : 0.f;
        __half h = __float2half(v);
        g_AhH[idx] = h;
        g_AhL[idx] = __float2half(v - __half2float(h));
    }
}

// ---------------- main kernel ----------------
// smem (bytes), MMA phase:
//   A(buf,plane) = buf*36864 + plane*18432   [0, 73728)   (128 rows x 144B)
//   B(buf)       = 73728 + buf*18432          [73728, 110592) (128 rows x 144B)
// EPI overlay:
//   lg  @0      : [128][64] f32 = 32768   (rows 0-63 bt0, 64-127 bt1; logits)
//   attH@32768  : [128][72] half = 18432
//   attL@51200  : 18432
//   bH  @69632  : [128][72] half = 18432   (xw / axw, hi)
//   bL  @88064  : 18432
//   scr @106496 : 8 warps x 1024 = 8192
//   dnl @114688 : 256
#define SMEM_BYTES 114944

__global__ __launch_bounds__(NTH, 2) void gat_wmma(float* __restrict__ out) {
    extern __shared__ char smc[];
    const uint32_t smb = smem_u32(smc);
    const int tid = threadIdx.x;
    const int warp = tid >> 5;
    const int lane = tid & 31;
    const int b2 = blockIdx.x * 2;

    float*  lg   = (float*)(smc + 0);
    __half* attH = (__half*)(smc + 32768);
    __half* attL = (__half*)(smc + 51200);
    __half* bHs  = (__half*)(smc + 69632);
    __half* bLs  = (__half*)(smc + 88064);
    float*  scrw = (float*)(smc + 106496 + warp * 1024);
    float*  dnl  = (float*)(smc + 114688);

    // main-GEMM warp grid: 8 M-tiles x 8 N-tiles; warp (wr,wc) owns 2M x 4N (nt = wc+2j)
    const int wr = warp >> 1, wc = warp & 1;
    const int mtb = wr * 2;
    // epilogue small-GEMM mapping: 2 units x 16 tiles, warp -> (bt, tile-row)
    const int ebt = warp >> 2, smt = warp & 3;

    for (int pass = 0; pass < 24; pass++) {
        const int l = pass >> 3, head = pass & 7;
        const float scl = (l == 0) ? 2.f : 1.f;

        // ---- zero A pad rows (62,63,126,127) x 2 planes x 2 bufs ----
        if (tid < 128) {
            int seg = tid & 7, r = (tid >> 3) & 3, plane = (tid >> 5) & 1, buf = (tid >> 6) & 1;
            int row = (r >> 1) * 64 + 62 + (r & 1);
            *(uint4*)(smc + buf * 36864 + plane * 18432 + row * 144 + seg * 16) =
                make_uint4(0, 0, 0, 0);
        }

        wmma::fragment<wmma::accumulator, 16, 16, 16, float> c[2][4];
        #pragma unroll
        for (int i = 0; i < 2; i++)
            #pragma unroll
            for (int j = 0; j < 4; j++) wmma::fill_fragment(c[i][j], 0.f);

        // ---- prefetch kt=0 into buf 0 ----
        {
            for (int u = tid; u < 2048; u += NTH) {
                int p = u >> 10, idx = u & 1023;
                int row = idx >> 3, seg = idx & 7;
                int nn = row & 63;
                if (nn < NN) {
                    const __half* src = (p ? g_xl : g_xh) +
                        ((size_t)(b2 + (row >> 6)) * NN + nn) * CIN + seg * 8;
                    CP_ASYNC16(smb + p * 18432 + row * 144 + seg * 16, src);
                }
            }
            for (int u = tid; u < 1024; u += NTH) {
                int row = u >> 3, seg = u & 7;
                const __half* src = g_Bh + ((size_t)(pass)*128 + row) * CIN + seg * 8;
                CP_ASYNC16(smb + 73728 + row * 144 + seg * 16, src);
            }
            CP_COMMIT();
        }

        // ---- K loop: 8 chunks of 64, double buffered ----
        for (int kt = 0; kt < 8; kt++) {
            const int buf = kt & 1;
            if (kt < 7) {
                const int nbuf = buf ^ 1;
                for (int u = tid; u < 2048; u += NTH) {
                    int p = u >> 10, idx = u & 1023;
                    int row = idx >> 3, seg = idx & 7;
                    int nn = row & 63;
                    if (nn < NN) {
                        const __half* src = (p ? g_xl : g_xh) +
                            ((size_t)(b2 + (row >> 6)) * NN + nn) * CIN + (kt + 1) * 64 + seg * 8;
                        CP_ASYNC16(smb + nbuf * 36864 + p * 18432 + row * 144 + seg * 16, src);
                    }
                }
                for (int u = tid; u < 1024; u += NTH) {
                    int row = u >> 3, seg = u & 7;
                    const __half* src = g_Bh + ((size_t)(pass)*128 + row) * CIN +
                                        (kt + 1) * 64 + seg * 8;
                    CP_ASYNC16(smb + 73728 + nbuf * 18432 + row * 144 + seg * 16, src);
                }
                CP_COMMIT();
                CP_WAIT(1);
            } else {
                CP_WAIT(0);
            }
            __syncthreads();

            const __half* Ah = (const __half*)(smc + buf * 36864);
            const __half* Al = (const __half*)(smc + buf * 36864 + 18432);
            const __half* Bs = (const __half*)(smc + 73728 + buf * 18432);
            #pragma unroll
            for (int k16 = 0; k16 < 4; k16++) {
                wmma::fragment<wmma::matrix_a, 16, 16, 16, __half, wmma::row_major> ah[2], al[2];
                #pragma unroll
                for (int i = 0; i < 2; i++) {
                    wmma::load_matrix_sync(ah[i], Ah + (mtb + i) * 16 * 72 + k16 * 16, 72);
                    wmma::load_matrix_sync(al[i], Al + (mtb + i) * 16 * 72 + k16 * 16, 72);
                }
                #pragma unroll
                for (int j = 0; j < 4; j++) {
                    int nt = wc + 2 * j;
                    wmma::fragment<wmma::matrix_b, 16, 16, 16, __half, wmma::col_major> b;
                    wmma::load_matrix_sync(b, Bs + nt * 16 * 72 + k16 * 16, 72);
                    wmma::mma_sync(c[0][j], ah[0], b, c[0][j]);
                    wmma::mma_sync(c[1][j], ah[1], b, c[1][j]);
                    wmma::mma_sync(c[0][j], al[0], b, c[0][j]);
                    wmma::mma_sync(c[1][j], al[1], b, c[1][j]);
                }
            }
            __syncthreads();
        }

        // ---- C store: logits -> lg (fp32); xw -> bH/bL (fp16 hi/lo, scl folded) ----
        #pragma unroll
        for (int i = 0; i < 2; i++)
            #pragma unroll
            for (int j = 0; j < 4; j++) {
                int mt = mtb + i;
                int nt = wc + 2 * j;
                if (nt < 4) {
                    wmma::store_matrix_sync(lg + mt * 16 * 64 + nt * 16, c[i][j], 64,
                                            wmma::mem_row_major);
                } else {
                    wmma::store_matrix_sync(scrw, c[i][j], 16, wmma::mem_row_major);
                    __syncwarp();
                    int cc = (nt - 4) * 16, rb = mt * 16;
                    #pragma unroll
                    for (int e = 0; e < 2; e++) {
                        int idx = lane * 8 + e * 4;
                        float4 v4 = *(const float4*)(scrw + idx);
                        int r = idx >> 4, cl = idx & 15;
                        float vs[4] = {v4.x, v4.y, v4.z, v4.w};
                        #pragma unroll
                        for (int q = 0; q < 4; q++) {
                            float v = scl * vs[q];
                            __half h = __float2half(v);
                            bHs[(rb + r) * 72 + cc + cl + q] = h;
                            bLs[(rb + r) * 72 + cc + cl + q] = __float2half(v - __half2float(h));
                        }
                    }
                    __syncwarp();
                }
            }
        if (tid < NN) dnl[tid] = g_dneg[l * NN + tid];
        __syncthreads();

        // ---- softmax: 256 thr = 2 units x 64 cols x 2 halves (no guard; cols 62/63 scratch) ----
        {
            int cc = tid >> 1, half = tid & 1;
            int bt = cc >> 6, m = cc & 63;
            float* col = lg + bt * 64 * 64 + m;
            int nlo = half * 31;
            float mx = -1e30f;
            #pragma unroll 1
            for (int n = nlo; n < nlo + 31; n++) {
                float v = dnl[n] * col[n * 64];
                v = (v > 0.f) ? v : 0.01f * v;
                col[n * 64] = v;
                mx = fmaxf(mx, v);
            }
            mx = fmaxf(mx, __shfl_xor_sync(0xffffffffu, mx, 1));
            float ssum = 0.f;
            #pragma unroll 1
            for (int n = nlo; n < nlo + 31; n++) {
                float e = __expf(col[n * 64] - mx);
                col[n * 64] = e;
                ssum += e;
            }
            ssum += __shfl_xor_sync(0xffffffffu, ssum, 1);
            float inv = 1.f / ssum;
            #pragma unroll 1
            for (int n = nlo; n < nlo + 31; n++) col[n * 64] *= inv;
        }
        __syncthreads();

        // ---- GEMM1 compute (l>0): axw tiles into f[] (reads bHL + global Ahat);
        //      then att conversion lg -> attHL (all threads) ----
        wmma::fragment<wmma::accumulator, 16, 16, 16, float> f[4];
        if (l > 0) {
            #pragma unroll
            for (int j = 0; j < 4; j++) wmma::fill_fragment(f[j], 0.f);
            const __half* ahg = g_AhH + l * 64 * 72;
            const __half* alg = g_AhL + l * 64 * 72;
            #pragma unroll
            for (int k16 = 0; k16 < 4; k16++) {
                wmma::fragment<wmma::matrix_a, 16, 16, 16, __half, wmma::row_major> aH, aL;
                wmma::load_matrix_sync(aH, ahg + smt * 16 * 72 + k16 * 16, 72);
                wmma::load_matrix_sync(aL, alg + smt * 16 * 72 + k16 * 16, 72);
                #pragma unroll
                for (int j = 0; j < 4; j++) {
                    wmma::fragment<wmma::matrix_b, 16, 16, 16, __half, wmma::row_major> bh, bl;
                    wmma::load_matrix_sync(bh, bHs + (ebt * 64 + k16 * 16) * 72 + j * 16, 72);
                    wmma::load_matrix_sync(bl, bLs + (ebt * 64 + k16 * 16) * 72 + j * 16, 72);
                    wmma::mma_sync(f[j], aH, bh, f[j]);
                    wmma::mma_sync(f[j], aH, bl, f[j]);
                    wmma::mma_sync(f[j], aL, bh, f[j]);
                }
            }
        }
        for (int i = tid; i < 8192; i += NTH) {
            int r = i >> 6, cl = i & 63;
            float a = lg[r * 64 + cl];
            __half ha = __float2half(a);
            attH[r * 72 + cl] = ha;
            attL[r * 72 + cl] = __float2half(a - __half2float(ha));
        }
        __syncthreads();

        // ---- (l>0) overwrite bHL with axw hi/lo ----
        if (l > 0) {
            #pragma unroll
            for (int j = 0; j < 4; j++) {
                wmma::store_matrix_sync(scrw, f[j], 16, wmma::mem_row_major);
                __syncwarp();
                int rb = ebt * 64 + smt * 16, cc = j * 16;
                #pragma unroll
                for (int e = 0; e < 2; e++) {
                    int idx = lane * 8 + e * 4;
                    float4 v4 = *(const float4*)(scrw + idx);
                    int r = idx >> 4, cl = idx & 15;
                    float vs[4] = {v4.x, v4.y, v4.z, v4.w};
                    #pragma unroll
                    for (int q = 0; q < 4; q++) {
                        float v = vs[q];
                        __half h = __float2half(v);
                        bHs[(rb + r) * 72 + cc + cl + q] = h;
                        bLs[(rb + r) * 72 + cc + cl + q] = __float2half(v - __half2float(h));
                    }
                }
                __syncwarp();
            }
        }
        __syncthreads();

        // ---- GEMM2: o = att @ axw -> lg ----
        {
            wmma::fragment<wmma::accumulator, 16, 16, 16, float> f2[4];
            #pragma unroll
            for (int j = 0; j < 4; j++) wmma::fill_fragment(f2[j], 0.f);
            #pragma unroll
            for (int k16 = 0; k16 < 4; k16++) {
                wmma::fragment<wmma::matrix_a, 16, 16, 16, __half, wmma::row_major> aH, aL;
                wmma::load_matrix_sync(aH, attH + (ebt * 64 + smt * 16) * 72 + k16 * 16, 72);
                wmma::load_matrix_sync(aL, attL + (ebt * 64 + smt * 16) * 72 + k16 * 16, 72);
                #pragma unroll
                for (int j = 0; j < 4; j++) {
                    wmma::fragment<wmma::matrix_b, 16, 16, 16, __half, wmma::row_major> bh, bl;
                    wmma::load_matrix_sync(bh, bHs + (ebt * 64 + k16 * 16) * 72 + j * 16, 72);
                    wmma::load_matrix_sync(bl, bLs + (ebt * 64 + k16 * 16) * 72 + j * 16, 72);
                    wmma::mma_sync(f2[j], aH, bh, f2[j]);
                    wmma::mma_sync(f2[j], aH, bl, f2[j]);
                    wmma::mma_sync(f2[j], aL, bh, f2[j]);
                }
            }
            #pragma unroll
            for (int j = 0; j < 4; j++)
                wmma::store_matrix_sync(lg + (ebt * 64 + smt * 16) * 64 + j * 16, f2[j], 64,
                                        wmma::mem_row_major);
        }
        __syncthreads();

        // ---- RMW out ----
        for (int i = tid; i < 2 * NN * 16; i += NTH) {
            int bt = (i >= NN * 16);
            int rem = i - bt * NN * 16;
            int n = rem >> 4, o4c = (rem & 15) * 4;
            float4 v = *(const float4*)(lg + (bt * 64 + n) * 64 + o4c);
            float4 add;
            add.x = fmaxf(v.x, 0.f); add.y = fmaxf(v.y, 0.f);
            add.z = fmaxf(v.z, 0.f); add.w = fmaxf(v.w, 0.f);
            float4* op = (float4*)(out + ((size_t)(b2 + bt) * NN + n) * 512 + head * 64 + o4c);
            if (l == 0) {
                *op = add;
            } else if (l == 1) {
                float4 o4v = *op;
                o4v.x += add.x; o4v.y += add.y; o4v.z += add.z; o4v.w += add.w;
                *op = o4v;
            } else {
                float4 o4v = *op;
                o4v.x = fmaxf(o4v.x + add.x, 0.f);
                o4v.y = fmaxf(o4v.y + add.y, 0.f);
                o4v.z = fmaxf(o4v.z + add.z, 0.f);
                o4v.w = fmaxf(o4v.w + add.w, 0.f);
                *op = o4v;
            }
        }
        __syncthreads();   // lg/bufs reused by next pass prefetch
    }
}

extern "C" void kernel_launch(void* const* d_in, const int* in_sizes, int n_in,
                              void* d_out, int out_size) {
    const float* x   = (const float*)d_in[0];
    const float* L   = (const float*)d_in[1];
    const float* Wal = (const float*)d_in[2];
    const float* W   = (const float*)d_in[3];
    float* out = (float*)d_out;

    cudaFuncSetAttribute(gat_wmma, cudaFuncAttributeMaxDynamicSharedMemorySize, SMEM_BYTES);
    conv_x<<<8192, 256>>>(x);
    conv_w<<<3072, 256>>>(Wal, W);
    precompute_adj<<<1, 256>>>(L);
    gat_wmma<<<NB / 2, NTH, SMEM_BYTES>>>(out);
}

// round 17
// speedup vs baseline: 9.1831x; 1.3191x over previous
#include <cuda_runtime.h>
#include <cuda_fp16.h>
#include <mma.h>
#include <cstdint>
#include <cstddef>

using namespace nvcuda;

#define NN 62
#define CIN 512
#define NLAY 3
#define NHEAD 8
#define CO 64
#define NB 2048
#define NTH 256

// ---------------- device global scratch ----------------
__device__ __half g_xh[(size_t)NB * NN * CIN];
__device__ __half g_Bh[NLAY * NHEAD * 128 * CIN];
__device__ __align__(32) __half g_AhH[NLAY * 64 * 72];
__device__ __align__(32) __half g_AhL[NLAY * 64 * 72];
__device__ float g_Ahat[NLAY * NN * NN];
__device__ float g_dneg[NLAY * NN];

// ---------------- helpers ----------------
__device__ __forceinline__ uint32_t smem_u32(const void* p) {
    uint32_t a;
    asm("{ .reg .u64 t; cvta.to.shared.u64 t, %1; cvt.u32.u64 %0, t; }" : "=r"(a) : "l"(p));
    return a;
}
#define CP_ASYNC16(dst, src) \
    asm volatile("cp.async.cg.shared.global [%0], [%1], 16;" :: "r"(dst), "l"(src) : "memory")
#define CP_COMMIT() asm volatile("cp.async.commit_group;" ::: "memory")
#define CP_WAIT(n)  asm volatile("cp.async.wait_group %0;" :: "n"(n) : "memory")

// ---------------- precompute kernels ----------------
__global__ void conv_x(const float* __restrict__ x) {
    size_t n8 = (size_t)NB * NN * CIN / 8;
    for (size_t i = blockIdx.x * (size_t)blockDim.x + threadIdx.x; i < n8;
         i += (size_t)gridDim.x * blockDim.x) {
        const float4* s = (const float4*)x + i * 2;
        float4 v0 = s[0], v1 = s[1];
        float f[8] = {v0.x, v0.y, v0.z, v0.w, v1.x, v1.y, v1.z, v1.w};
        alignas(16) __half h[8];
        #pragma unroll
        for (int j = 0; j < 8; j++) h[j] = __float2half(f[j]);
        *(uint4*)(g_xh + i * 8) = *(const uint4*)h;
    }
}
// g_Bh[(l*8+head)][c(0..127)][k]: c<62 -> Walpha col c, c in [64,128) -> W col c-64, else 0
__global__ void conv_w(const float* __restrict__ Wal, const float* __restrict__ Wo) {
    int total = NLAY * NHEAD * 128 * CIN;
    for (int i = blockIdx.x * blockDim.x + threadIdx.x; i < total; i += gridDim.x * blockDim.x) {
        int k = i & 511;
        int t = i >> 9;
        int c = t & 127;
        int lh = t >> 7;
        float v = 0.f;
        if (c < NN) v = Wal[((size_t)lh * CIN + k) * NN + c];
        else if (c >= 64) v = Wo[((size_t)lh * CIN + k) * CO + (c - 64)];
        g_Bh[i] = __float2half(v);
    }
}
__global__ void precompute_adj(const float* __restrict__ L) {
    __shared__ float D1s[NN];
    int tid = threadIdx.x;
    if (tid < NN) {
        float s = 0.f;
        for (int m = 0; m < NN; m++) s += L[tid * NN + m];
        D1s[tid] = s;
    }
    __syncthreads();
    if (tid < NN) {
        g_dneg[tid] = 1.0f;
        float d1 = D1s[tid];
        g_dneg[NN + tid] = (d1 == 0.f) ? 0.f : (1.f / d1);
        float d2 = 0.f;
        for (int k = 0; k < NN; k++) d2 += L[tid * NN + k] * D1s[k];
        g_dneg[2 * NN + tid] = (d2 == 0.f) ? 0.f : (1.f / d2);
    }
    for (int idx = tid; idx < NN * NN; idx += blockDim.x) {
        int n = idx / NN, m = idx - n * NN;
        float eye = (n == m) ? 1.f : 0.f;
        g_Ahat[idx] = 2.f * eye;
        g_Ahat[NN * NN + idx] = L[idx] + eye;
        float a2 = 0.f;
        for (int k = 0; k < NN; k++) a2 += L[n * NN + k] * L[k * NN + m];
        g_Ahat[2 * NN * NN + idx] = a2 + eye;
    }
    __syncthreads();
    // fp16 hi/lo split of Ahat, padded [64][72], pad = 0
    for (int idx = tid; idx < NLAY * 64 * 72; idx += blockDim.x) {
        int l = idx / (64 * 72), rem = idx - l * 64 * 72;
        int r = rem / 72, c = rem - r * 72;
        float v = (r < NN && c < NN) ? g_Ahat[l * NN * NN + r * NN + c] : 0.f;
        __half h = __float2half(v);
        g_AhH[idx] = h;
        g_AhL[idx] = __float2half(v - __half2float(h));
    }
}

// ---------------- main kernel ----------------
// smem (bytes), MMA phase:
//   A(buf) = buf*18432            [0, 36864)    (128 rows x 144B)
//   B(buf) = 36864 + buf*18432    [36864, 73728)
// EPI overlay:
//   lg  @0      : [128][64] f32 = 32768
//   attH@32768  : [128][72] half = 18432
//   attL@51200  : 18432
//   bH  @69632  : 18432
//   bL  @88064  : 18432
//   scr @106496 : 8 warps x 1024 = 8192
//   dnl @114688 : 256
#define SMEM_BYTES 114944

__global__ __launch_bounds__(NTH, 2) void gat_wmma(float* __restrict__ out) {
    extern __shared__ char smc[];
    const uint32_t smb = smem_u32(smc);
    const int tid = threadIdx.x;
    const int warp = tid >> 5;
    const int lane = tid & 31;
    const int b2 = blockIdx.x * 2;

    float*  lg   = (float*)(smc + 0);
    __half* attH = (__half*)(smc + 32768);
    __half* attL = (__half*)(smc + 51200);
    __half* bHs  = (__half*)(smc + 69632);
    __half* bLs  = (__half*)(smc + 88064);
    float*  scrw = (float*)(smc + 106496 + warp * 1024);
    float*  dnl  = (float*)(smc + 114688);

    // main-GEMM warp grid: 8 M-tiles x 8 N-tiles; warp (wr,wc) owns 2M x 4N (nt = wc+2j)
    const int wr = warp >> 1, wc = warp & 1;
    const int mtb = wr * 2;
    // epilogue small-GEMM mapping: 2 units x 16 tiles, warp -> (bt, tile-row)
    const int ebt = warp >> 2, smt = warp & 3;

    for (int pass = 0; pass < 24; pass++) {
        const int l = pass >> 3, head = pass & 7;
        const float scl = (l == 0) ? 2.f : 1.f;

        // ---- zero A pad rows (62,63,126,127) x 2 bufs ----
        if (tid < 64) {
            int seg = tid & 7, r = (tid >> 3) & 3, buf = (tid >> 5) & 1;
            int row = (r >> 1) * 64 + 62 + (r & 1);
            *(uint4*)(smc + buf * 18432 + row * 144 + seg * 16) = make_uint4(0, 0, 0, 0);
        }

        wmma::fragment<wmma::accumulator, 16, 16, 16, float> c[2][4];
        #pragma unroll
        for (int i = 0; i < 2; i++)
            #pragma unroll
            for (int j = 0; j < 4; j++) wmma::fill_fragment(c[i][j], 0.f);

        // ---- prefetch kt=0 into buf 0 ----
        {
            for (int u = tid; u < 1024; u += NTH) {
                int row = u >> 3, seg = u & 7;
                int nn = row & 63;
                if (nn < NN) {
                    const __half* src = g_xh +
                        ((size_t)(b2 + (row >> 6)) * NN + nn) * CIN + seg * 8;
                    CP_ASYNC16(smb + row * 144 + seg * 16, src);
                }
            }
            for (int u = tid; u < 1024; u += NTH) {
                int row = u >> 3, seg = u & 7;
                const __half* src = g_Bh + ((size_t)pass * 128 + row) * CIN + seg * 8;
                CP_ASYNC16(smb + 36864 + row * 144 + seg * 16, src);
            }
            CP_COMMIT();
        }

        // ---- K loop: 8 chunks of 64, double buffered ----
        for (int kt = 0; kt < 8; kt++) {
            const int buf = kt & 1;
            if (kt < 7) {
                const int nbuf = buf ^ 1;
                for (int u = tid; u < 1024; u += NTH) {
                    int row = u >> 3, seg = u & 7;
                    int nn = row & 63;
                    if (nn < NN) {
                        const __half* src = g_xh +
                            ((size_t)(b2 + (row >> 6)) * NN + nn) * CIN + (kt + 1) * 64 + seg * 8;
                        CP_ASYNC16(smb + nbuf * 18432 + row * 144 + seg * 16, src);
                    }
                }
                for (int u = tid; u < 1024; u += NTH) {
                    int row = u >> 3, seg = u & 7;
                    const __half* src = g_Bh + ((size_t)pass * 128 + row) * CIN +
                                        (kt + 1) * 64 + seg * 8;
                    CP_ASYNC16(smb + 36864 + nbuf * 18432 + row * 144 + seg * 16, src);
                }
                CP_COMMIT();
                CP_WAIT(1);
            } else {
                CP_WAIT(0);
            }
            __syncthreads();

            const __half* Ah = (const __half*)(smc + buf * 18432);
            const __half* Bs = (const __half*)(smc + 36864 + buf * 18432);
            #pragma unroll
            for (int k16 = 0; k16 < 4; k16++) {
                wmma::fragment<wmma::matrix_a, 16, 16, 16, __half, wmma::row_major> ah[2];
                #pragma unroll
                for (int i = 0; i < 2; i++)
                    wmma::load_matrix_sync(ah[i], Ah + (mtb + i) * 16 * 72 + k16 * 16, 72);
                #pragma unroll
                for (int j = 0; j < 4; j++) {
                    int nt = wc + 2 * j;
                    wmma::fragment<wmma::matrix_b, 16, 16, 16, __half, wmma::col_major> b;
                    wmma::load_matrix_sync(b, Bs + nt * 16 * 72 + k16 * 16, 72);
                    wmma::mma_sync(c[0][j], ah[0], b, c[0][j]);
                    wmma::mma_sync(c[1][j], ah[1], b, c[1][j]);
                }
            }
            __syncthreads();
        }

        // ---- C store: logits -> lg (fp32); xw -> bH/bL (fp16 hi/lo, scl folded) ----
        #pragma unroll
        for (int i = 0; i < 2; i++)
            #pragma unroll
            for (int j = 0; j < 4; j++) {
                int mt = mtb + i;
                int nt = wc + 2 * j;
                if (nt < 4) {
                    wmma::store_matrix_sync(lg + mt * 16 * 64 + nt * 16, c[i][j], 64,
                                            wmma::mem_row_major);
                } else {
                    wmma::store_matrix_sync(scrw, c[i][j], 16, wmma::mem_row_major);
                    __syncwarp();
                    int cc = (nt - 4) * 16, rb = mt * 16;
                    #pragma unroll
                    for (int e = 0; e < 2; e++) {
                        int idx = lane * 8 + e * 4;
                        float4 v4 = *(const float4*)(scrw + idx);
                        int r = idx >> 4, cl = idx & 15;
                        float vs[4] = {v4.x, v4.y, v4.z, v4.w};
                        #pragma unroll
                        for (int q = 0; q < 4; q++) {
                            float v = scl * vs[q];
                            __half h = __float2half(v);
                            bHs[(rb + r) * 72 + cc + cl + q] = h;
                            bLs[(rb + r) * 72 + cc + cl + q] = __float2half(v - __half2float(h));
                        }
                    }
                    __syncwarp();
                }
            }
        if (tid < NN) dnl[tid] = g_dneg[l * NN + tid];
        __syncthreads();

        // ---- softmax: 256 thr = 2 units x 64 cols x 2 halves (no guard; cols 62/63 scratch) ----
        {
            int cc = tid >> 1, half = tid & 1;
            int bt = cc >> 6, m = cc & 63;
            float* col = lg + bt * 64 * 64 + m;
            int nlo = half * 31;
            float mx = -1e30f;
            #pragma unroll 1
            for (int n = nlo; n < nlo + 31; n++) {
                float v = dnl[n] * col[n * 64];
                v = (v > 0.f) ? v : 0.01f * v;
                col[n * 64] = v;
                mx = fmaxf(mx, v);
            }
            mx = fmaxf(mx, __shfl_xor_sync(0xffffffffu, mx, 1));
            float ssum = 0.f;
            #pragma unroll 1
            for (int n = nlo; n < nlo + 31; n++) {
                float e = __expf(col[n * 64] - mx);
                col[n * 64] = e;
                ssum += e;
            }
            ssum += __shfl_xor_sync(0xffffffffu, ssum, 1);
            float inv = 1.f / ssum;
            #pragma unroll 1
            for (int n = nlo; n < nlo + 31; n++) col[n * 64] *= inv;
        }
        __syncthreads();

        // ---- GEMM1 compute (l>0): axw tiles into f[] (reads bHL + global Ahat);
        //      then att conversion lg -> attHL (all threads) ----
        wmma::fragment<wmma::accumulator, 16, 16, 16, float> f[4];
        if (l > 0) {
            #pragma unroll
            for (int j = 0; j < 4; j++) wmma::fill_fragment(f[j], 0.f);
            const __half* ahg = g_AhH + l * 64 * 72;
            const __half* alg = g_AhL + l * 64 * 72;
            #pragma unroll
            for (int k16 = 0; k16 < 4; k16++) {
                wmma::fragment<wmma::matrix_a, 16, 16, 16, __half, wmma::row_major> aH, aL;
                wmma::load_matrix_sync(aH, ahg + smt * 16 * 72 + k16 * 16, 72);
                wmma::load_matrix_sync(aL, alg + smt * 16 * 72 + k16 * 16, 72);
                #pragma unroll
                for (int j = 0; j < 4; j++) {
                    wmma::fragment<wmma::matrix_b, 16, 16, 16, __half, wmma::row_major> bh, bl;
                    wmma::load_matrix_sync(bh, bHs + (ebt * 64 + k16 * 16) * 72 + j * 16, 72);
                    wmma::load_matrix_sync(bl, bLs + (ebt * 64 + k16 * 16) * 72 + j * 16, 72);
                    wmma::mma_sync(f[j], aH, bh, f[j]);
                    wmma::mma_sync(f[j], aH, bl, f[j]);
                    wmma::mma_sync(f[j], aL, bh, f[j]);
                }
            }
        }
        for (int i = tid; i < 8192; i += NTH) {
            int r = i >> 6, cl = i & 63;
            float a = lg[r * 64 + cl];
            __half ha = __float2half(a);
            attH[r * 72 + cl] = ha;
            attL[r * 72 + cl] = __float2half(a - __half2float(ha));
        }
        __syncthreads();

        // ---- (l>0) overwrite bHL with axw hi/lo ----
        if (l > 0) {
            #pragma unroll
            for (int j = 0; j < 4; j++) {
                wmma::store_matrix_sync(scrw, f[j], 16, wmma::mem_row_major);
                __syncwarp();
                int rb = ebt * 64 + smt * 16, cc = j * 16;
                #pragma unroll
                for (int e = 0; e < 2; e++) {
                    int idx = lane * 8 + e * 4;
                    float4 v4 = *(const float4*)(scrw + idx);
                    int r = idx >> 4, cl = idx & 15;
                    float vs[4] = {v4.x, v4.y, v4.z, v4.w};
                    #pragma unroll
                    for (int q = 0; q < 4; q++) {
                        float v = vs[q];
                        __half h = __float2half(v);
                        bHs[(rb + r) * 72 + cc + cl + q] = h;
                        bLs[(rb + r) * 72 + cc + cl + q] = __float2half(v - __half2float(h));
                    }
                }
                __syncwarp();
            }
        }
        __syncthreads();

        // ---- GEMM2: o = att @ axw -> lg ----
        {
            wmma::fragment<wmma::accumulator, 16, 16, 16, float> f2[4];
            #pragma unroll
            for (int j = 0; j < 4; j++) wmma::fill_fragment(f2[j], 0.f);
            #pragma unroll
            for (int k16 = 0; k16 < 4; k16++) {
                wmma::fragment<wmma::matrix_a, 16, 16, 16, __half, wmma::row_major> aH, aL;
                wmma::load_matrix_sync(aH, attH + (ebt * 64 + smt * 16) * 72 + k16 * 16, 72);
                wmma::load_matrix_sync(aL, attL + (ebt * 64 + smt * 16) * 72 + k16 * 16, 72);
                #pragma unroll
                for (int j = 0; j < 4; j++) {
                    wmma::fragment<wmma::matrix_b, 16, 16, 16, __half, wmma::row_major> bh, bl;
                    wmma::load_matrix_sync(bh, bHs + (ebt * 64 + k16 * 16) * 72 + j * 16, 72);
                    wmma::load_matrix_sync(bl, bLs + (ebt * 64 + k16 * 16) * 72 + j * 16, 72);
                    wmma::mma_sync(f2[j], aH, bh, f2[j]);
                    wmma::mma_sync(f2[j], aH, bl, f2[j]);
                    wmma::mma_sync(f2[j], aL, bh, f2[j]);
                }
            }
            #pragma unroll
            for (int j = 0; j < 4; j++)
                wmma::store_matrix_sync(lg + (ebt * 64 + smt * 16) * 64 + j * 16, f2[j], 64,
                                        wmma::mem_row_major);
        }
        __syncthreads();

        // ---- RMW out ----
        for (int i = tid; i < 2 * NN * 16; i += NTH) {
            int bt = (i >= NN * 16);
            int rem = i - bt * NN * 16;
            int n = rem >> 4, o4c = (rem & 15) * 4;
            float4 v = *(const float4*)(lg + (bt * 64 + n) * 64 + o4c);
            float4 add;
            add.x = fmaxf(v.x, 0.f); add.y = fmaxf(v.y, 0.f);
            add.z = fmaxf(v.z, 0.f); add.w = fmaxf(v.w, 0.f);
            float4* op = (float4*)(out + ((size_t)(b2 + bt) * NN + n) * 512 + head * 64 + o4c);
            if (l == 0) {
                *op = add;
            } else if (l == 1) {
                float4 o4v = *op;
                o4v.x += add.x; o4v.y += add.y; o4v.z += add.z; o4v.w += add.w;
                *op = o4v;
            } else {
                float4 o4v = *op;
                o4v.x = fmaxf(o4v.x + add.x, 0.f);
                o4v.y = fmaxf(o4v.y + add.y, 0.f);
                o4v.z = fmaxf(o4v.z + add.z, 0.f);
                o4v.w = fmaxf(o4v.w + add.w, 0.f);
                *op = o4v;
            }
        }
        __syncthreads();   // lg/bufs reused by next pass prefetch
    }
}

extern "C" void kernel_launch(void* const* d_in, const int* in_sizes, int n_in,
                              void* d_out, int out_size) {
    const float* x   = (const float*)d_in[0];
    const float* L   = (const float*)d_in[1];
    const float* Wal = (const float*)d_in[2];
    const float* W   = (const float*)d_in[3];
    float* out = (float*)d_out;

    cudaFuncSetAttribute(gat_wmma, cudaFuncAttributeMaxDynamicSharedMemorySize, SMEM_BYTES);
    conv_x<<<8192, 256>>>(x);
    conv_w<<<3072, 256>>>(Wal, W);
    precompute_adj<<<1, 256>>>(L);
    gat_wmma<<<NB / 2, NTH, SMEM_BYTES>>>(out);
}